// round 3
// baseline (speedup 1.0000x reference)
#include <cuda_runtime.h>
#include <cstdint>
#include <cstddef>

// Problem constants
#define B_   32
#define T_   512
#define E_   300
#define EP_  320              // padded embedding K (mult of 32)
#define H_   1024
#define G4_  4096             // 4*H
#define M_   (B_*T_)          // 16384 token rows
#define NCTA_REC 128

// ---------------- scratch (device globals; no allocation allowed) ----------
__device__ uint32_t g_x   [(size_t)M_ * EP_];      // embedded inputs (tf32)
__device__ uint32_t g_wA  [(size_t)G4_ * 2048];    // converted w_ih (dir f)
__device__ uint32_t g_wB  [(size_t)G4_ * 2048];    // converted w_ih (dir b)
__device__ uint32_t g_whF [(size_t)G4_ * H_];      // converted w_hh fwd
__device__ uint32_t g_whB [(size_t)G4_ * H_];      // converted w_hh bwd
__device__ float    g_xpF [(size_t)M_ * G4_];      // input projection fwd
__device__ float    g_xpB [(size_t)M_ * G4_];      // input projection bwd
__device__ uint32_t g_out0[(size_t)M_ * 2 * H_];   // layer0 output (tf32)
__device__ uint32_t g_hF  [B_ * H_];
__device__ uint32_t g_hB  [B_ * H_];
__device__ unsigned g_cnt [8 * 32];                // striped barrier counters
__device__ unsigned g_cntm;                        // master counter
__device__ volatile unsigned g_bar_gen;            // barrier generation (monotonic)

// ---------------- helpers ---------------------------------------------------
__device__ __forceinline__ uint32_t f2tf(float f) {
    uint32_t u;
    asm("cvt.rna.tf32.f32 %0, %1;" : "=r"(u) : "f"(f));
    return u;
}

__device__ __forceinline__ void mma8(float* c, const uint32_t* a, const uint32_t* b) {
    asm volatile(
        "mma.sync.aligned.m16n8k8.row.col.f32.tf32.tf32.f32 "
        "{%0,%1,%2,%3},{%4,%5,%6,%7},{%8,%9},{%0,%1,%2,%3};"
        : "+f"(c[0]), "+f"(c[1]), "+f"(c[2]), "+f"(c[3])
        : "r"(a[0]), "r"(a[1]), "r"(a[2]), "r"(a[3]), "r"(b[0]), "r"(b[1]));
}

__device__ __forceinline__ float sigmoidf_(float x) { return 1.f / (1.f + __expf(-x)); }

__device__ __forceinline__ uint32_t s2u(const void* p) {
    uint32_t r;
    asm("{ .reg .u64 t; cvta.to.shared.u64 t, %1; cvt.u32.u64 %0, t; }" : "=r"(r) : "l"(p));
    return r;
}
__device__ __forceinline__ void cp16(void* smem, const void* gmem) {
    asm volatile("cp.async.cg.shared.global [%0], [%1], 16;\n" :: "r"(s2u(smem)), "l"(gmem));
}
__device__ __forceinline__ void cp_commit() { asm volatile("cp.async.commit_group;"); }
template<int N> __device__ __forceinline__ void cp_wait() {
    asm volatile("cp.async.wait_group %0;" :: "n"(N));
}

// Striped grid barrier; grid is exactly NCTA_REC co-resident CTAs.
// Monotonic epochs: no counter resets, safe across kernel instances & replays.
__device__ __forceinline__ void grid_barrier(unsigned epoch) {
    __threadfence();                       // each thread fences its own h stores
    __syncthreads();
    if (threadIdx.x == 0) {
        unsigned s = (blockIdx.x & 7) * 32;            // 8 stripes, 128B apart
        unsigned v = atomicAdd(&g_cnt[s], 1u) + 1u;
        if (v == 16u * epoch) {                        // last arrival in stripe
            unsigned a = atomicAdd(&g_cntm, 1u) + 1u;
            if (a == 8u * epoch) {                     // last stripe
                __threadfence();
                g_bar_gen = epoch;
            }
        }
        while (g_bar_gen < epoch) { }
    }
    __syncthreads();
}

// ---------------- kernel 1: embedding gather (emit tf32, pad to 320) -------
__global__ __launch_bounds__(256) void gather_kernel(
    const int* __restrict__ tok, const float* __restrict__ emb, uint32_t* __restrict__ x)
{
    int i = blockIdx.x * 256 + threadIdx.x;
    if (i >= M_ * EP_) return;
    int bt = i / EP_;
    int e  = i - bt * EP_;
    x[i] = (e < E_) ? f2tf(emb[(size_t)tok[bt] * E_ + e]) : 0u;
}

// ---------------- kernel 1b: fp32 -> tf32 convert (with K padding) ---------
__global__ __launch_bounds__(256) void conv_tf32(
    const float* __restrict__ src, uint32_t* __restrict__ dst, int N, int K, int Kp)
{
    int i = blockIdx.x * 256 + threadIdx.x;
    if (i >= N * Kp) return;
    int n = i / Kp, k = i - n * Kp;
    dst[i] = (k < K) ? f2tf(src[(size_t)n * K + k]) : 0u;
}

// vectorized convert for K == Kp cases (elem count multiple of 4)
__global__ __launch_bounds__(256) void conv_tf32_v4(
    const float4* __restrict__ src, uint4* __restrict__ dst, int n4)
{
    int i = blockIdx.x * 256 + threadIdx.x;
    if (i >= n4) return;
    float4 v = src[i];
    uint4 o;
    o.x = f2tf(v.x); o.y = f2tf(v.y); o.z = f2tf(v.z); o.w = f2tf(v.w);
    dst[i] = o;
}

// ---------------- kernel 2: tf32 GEMM, cp.async 3-stage, BK=32 -------------
#define GST 3
#define GEMM_SMEM (2 * GST * 128 * 36 * 4)
__global__ __launch_bounds__(256, 2) void gemm_tf32(
    const uint32_t* __restrict__ A, const uint32_t* __restrict__ Bw,
    const float* __restrict__ bias1, const float* __restrict__ bias2,
    float* __restrict__ C, int Ka)
{
    extern __shared__ char smraw[];
    uint32_t* As = (uint32_t*)smraw;              // GST * 128 * 36
    uint32_t* Bs = As + GST * 128 * 36;

    const int tid = threadIdx.x, warp = tid >> 5, lane = tid & 31;
    const int m0 = blockIdx.y * 128, n0 = blockIdx.x * 128;
    const int wm = (warp >> 1) * 32, wn = (warp & 1) * 64;
    const uint32_t* Ag = A + (size_t)m0 * Ka;
    const uint32_t* Bg = Bw + (size_t)n0 * Ka;

    float acc[2][8][4];
#pragma unroll
    for (int i = 0; i < 2; i++)
#pragma unroll
        for (int j = 0; j < 8; j++)
#pragma unroll
            for (int k = 0; k < 4; k++) acc[i][j][k] = 0.f;

    auto issue = [&](int st, int kc) {
#pragma unroll
        for (int i = 0; i < 4; i++) {
            int seg = tid + i * 256;             // 1024 segs
            int row = seg >> 3, c4 = (seg & 7) * 4;
            cp16(As + st * 128 * 36 + row * 36 + c4, Ag + (size_t)row * Ka + kc + c4);
            cp16(Bs + st * 128 * 36 + row * 36 + c4, Bg + (size_t)row * Ka + kc + c4);
        }
    };

    const int nc = Ka >> 5;
    issue(0, 0);  cp_commit();
    issue(1, 32); cp_commit();

    for (int c = 0; c < nc; c++) {
        if (c + 1 < nc) cp_wait<1>(); else cp_wait<0>();
        __syncthreads();
        if (c + 2 < nc) { issue((c + 2) % GST, (c + 2) * 32); cp_commit(); }

        const uint32_t* ab = As + (c % GST) * 128 * 36;
        const uint32_t* bb = Bs + (c % GST) * 128 * 36;
#pragma unroll
        for (int kk = 0; kk < 32; kk += 8) {
            int kq = kk + (lane & 3);
            uint32_t af[2][4], bf[8][2];
#pragma unroll
            for (int mt = 0; mt < 2; mt++) {
                int r = wm + mt * 16 + (lane >> 2);
                af[mt][0] = ab[r * 36 + kq];
                af[mt][1] = ab[(r + 8) * 36 + kq];
                af[mt][2] = ab[r * 36 + kq + 4];
                af[mt][3] = ab[(r + 8) * 36 + kq + 4];
            }
#pragma unroll
            for (int nt = 0; nt < 8; nt++) {
                int r = wn + nt * 8 + (lane >> 2);
                bf[nt][0] = bb[r * 36 + kq];
                bf[nt][1] = bb[r * 36 + kq + 4];
            }
#pragma unroll
            for (int mt = 0; mt < 2; mt++)
#pragma unroll
                for (int nt = 0; nt < 8; nt++)
                    mma8(acc[mt][nt], af[mt], bf[nt]);
        }
    }

#pragma unroll
    for (int mt = 0; mt < 2; mt++)
#pragma unroll
        for (int nt = 0; nt < 8; nt++) {
            int row = m0 + wm + mt * 16 + (lane >> 2);
            int col = n0 + wn + nt * 8 + 2 * (lane & 3);
            float bv0 = bias1[col] + bias2[col];
            float bv1 = bias1[col + 1] + bias2[col + 1];
            C[(size_t)row * G4_ + col]           = acc[mt][nt][0] + bv0;
            C[(size_t)row * G4_ + col + 1]       = acc[mt][nt][1] + bv1;
            C[(size_t)(row + 8) * G4_ + col]     = acc[mt][nt][2] + bv0;
            C[(size_t)(row + 8) * G4_ + col + 1] = acc[mt][nt][3] + bv1;
        }
}

// ---------------- kernel 3: persistent bi-LSTM layer -----------------------
// 128 CTAs: [0,64) fwd, [64,128) bwd. Each CTA owns 16 hidden cols (64 gate
// rows). First KPC k-chunks (of 64) of W_hh stay resident in SMEM; the rest
// and the h vector stream through 3-slot cp.async rings, distance-2 issue,
// one syncthreads per chunk.
#define KPC    7                 // persistent k-chunks
#define WPSTR  452               // 7*64 + 4 pad (mod 32 == 4, conflict-free)
#define HSTR   68
#define WSTR   68
#define LSTM_SMEM ((64*WPSTR + 3*64*WSTR + 3*32*HSTR) * 4 + 32*64*4 + 512*4 + 512*4 + 128)
__global__ __launch_bounds__(256) void lstm_layer_kernel(
    const float* __restrict__ xpF, const float* __restrict__ xpB,
    const uint32_t* __restrict__ WhF, const uint32_t* __restrict__ WhB,
    const int* __restrict__ lengths,
    uint32_t* __restrict__ out,           // (B*T) x 2H tf32, or nullptr
    uint32_t* __restrict__ hF, uint32_t* __restrict__ hB)
{
    extern __shared__ char smraw[];
    uint32_t* WP  = (uint32_t*)smraw;            // [64][WPSTR] persistent W
    uint32_t* WSR = WP + 64 * WPSTR;             // [3][64][WSTR] streamed W ring
    uint32_t* HR  = WSR + 3 * 64 * WSTR;         // [3][32][HSTR] h ring
    float*    GS  = (float*)(HR + 3 * 32 * HSTR);// [32][64] gates
    float*    CST = GS + 32 * 64;                // [512]
    float*    HST = CST + 512;                   // [512]
    int*      SLEN = (int*)(HST + 512);          // [32]

    const int tid = threadIdx.x, warp = tid >> 5, lane = tid & 31;
    const int cta = blockIdx.x;
    const int dir = cta >> 6;
    const int j0  = (cta & 63) * 16;
    const float*    xp   = dir ? xpB : xpF;
    const uint32_t* Wh   = dir ? WhB : WhF;
    uint32_t*       hdir = dir ? hB : hF;

    unsigned epoch = g_bar_gen;                  // monotonic base (pre-barrier)

    // init state + persistent W + lengths
    for (int p = tid; p < 512; p += 256) {
        int b = p >> 4, jl = p & 15;
        CST[p] = 0.f; HST[p] = 0.f;
        hdir[b * H_ + j0 + jl] = 0u;
    }
    if (tid < 32) SLEN[tid] = lengths[tid];
    for (int i = tid; i < 64 * (KPC * 64); i += 256) {
        int r = i / (KPC * 64), k = i - r * (KPC * 64);
        WP[r * WPSTR + k] = Wh[((size_t)((r >> 4) * H_ + j0 + (r & 15))) * H_ + k];
    }
    grid_barrier(++epoch);

    auto issueH = [&](int c) {
        uint32_t* dst = HR + (c % 3) * 32 * HSTR;
        const uint32_t* src = hdir + c * 64;
#pragma unroll
        for (int i = 0; i < 2; i++) {
            int seg = tid + i * 256;            // 512 segs of 16B
            int row = seg >> 4, c4 = (seg & 15) * 4;
            cp16(dst + row * HSTR + c4, src + row * H_ + c4);
        }
    };
    auto issueW = [&](int c) {
        uint32_t* dst = WSR + (c % 3) * 64 * WSTR;
#pragma unroll
        for (int i = 0; i < 4; i++) {
            int seg = tid + i * 256;            // 1024 segs
            int row = seg >> 4, c4 = (seg & 15) * 4;
            cp16(dst + row * WSTR + c4,
                 Wh + ((size_t)((row >> 4) * H_ + j0 + (row & 15))) * H_ + c * 64 + c4);
        }
    };

    for (int t = 0; t < T_; t++) {
        // prefetch this step's xp gate inputs into registers
        float xr[2][4];
#pragma unroll
        for (int p2 = 0; p2 < 2; p2++) {
            int p = tid + p2 * 256, b = p >> 4, jl = p & 15;
            int len = SLEN[b];
            int teff = dir ? ((t < len) ? (len - 1 - t) : 0) : t;
            const float* xb = xp + ((size_t)(b * T_ + teff)) * G4_ + j0 + jl;
            xr[p2][0] = __ldcs(xb);
            xr[p2][1] = __ldcs(xb + H_);
            xr[p2][2] = __ldcs(xb + 2 * H_);
            xr[p2][3] = __ldcs(xb + 3 * H_);
        }

        // pipeline prologue: chunks 0,1 (both persistent-W, H only)
        issueH(0); cp_commit();
        issueH(1); cp_commit();

        float acc[2][4];
#pragma unroll
        for (int mt = 0; mt < 2; mt++)
#pragma unroll
            for (int k = 0; k < 4; k++) acc[mt][k] = 0.f;

        for (int c = 0; c < 16; c++) {
            cp_wait<1>();
            __syncthreads();
            // issue chunk c+2 (slot (c+2)%3 was consumed in chunk c-1)
            if (c + 2 < 16) {
                issueH(c + 2);
                if (c + 2 >= KPC) issueW(c + 2);
            }
            cp_commit();                         // unconditional: uniform groups

            const uint32_t* hb = HR + (c % 3) * 32 * HSTR;
            const uint32_t* wb; int wstr;
            if (c < KPC) { wb = WP + c * 64;              wstr = WPSTR; }
            else         { wb = WSR + (c % 3) * 64 * WSTR; wstr = WSTR; }
            const uint32_t* wrow = wb + (warp * 8 + (lane >> 2)) * wstr;
#pragma unroll
            for (int kk = 0; kk < 64; kk += 8) {
                int kq = kk + (lane & 3);
                uint32_t bf[2] = { wrow[kq], wrow[kq + 4] };
#pragma unroll
                for (int mt = 0; mt < 2; mt++) {
                    int r = mt * 16 + (lane >> 2);
                    uint32_t af[4] = { hb[r * HSTR + kq], hb[(r + 8) * HSTR + kq],
                                       hb[r * HSTR + kq + 4], hb[(r + 8) * HSTR + kq + 4] };
                    mma8(acc[mt], af, bf);
                }
            }
        }

        // dump gate fragments (each warp owns its 8 columns of GS)
        {
            int rowb = lane >> 2, colb = warp * 8 + 2 * (lane & 3);
#pragma unroll
            for (int mt = 0; mt < 2; mt++) {
                GS[(mt * 16 + rowb) * 64 + colb]         = acc[mt][0];
                GS[(mt * 16 + rowb) * 64 + colb + 1]     = acc[mt][1];
                GS[(mt * 16 + rowb + 8) * 64 + colb]     = acc[mt][2];
                GS[(mt * 16 + rowb + 8) * 64 + colb + 1] = acc[mt][3];
            }
        }
        __syncthreads();

        // LSTM cell elementwise
#pragma unroll
        for (int p2 = 0; p2 < 2; p2++) {
            int p = tid + p2 * 256, b = p >> 4, jl = p & 15;
            int len = SLEN[b];
            bool msk = (t < len);
            float gi = GS[b * 64 + jl]      + xr[p2][0];
            float gf = GS[b * 64 + 16 + jl] + xr[p2][1];
            float gg = GS[b * 64 + 32 + jl] + xr[p2][2];
            float go = GS[b * 64 + 48 + jl] + xr[p2][3];
            if (msk) {
                float ii = sigmoidf_(gi), ff = sigmoidf_(gf);
                float gv = tanhf(gg),     oo = sigmoidf_(go);
                float cn = ff * CST[p] + ii * gv;
                float hn = oo * tanhf(cn);
                CST[p] = cn; HST[p] = hn;
                hdir[b * H_ + j0 + jl] = f2tf(hn);
            }
            if (out) {
                int pout = dir ? ((t < len) ? (len - 1 - t) : t) : t;
                out[((size_t)(b * T_ + pout)) * (2 * H_) + dir * H_ + j0 + jl] = f2tf(HST[p]);
            }
        }
        grid_barrier(++epoch);
    }
}

// ---------------- kernel 4: final linear  out = [h2b, h2f] @ lin_w^T + b ---
__global__ __launch_bounds__(256) void final_linear_kernel(
    const uint32_t* __restrict__ hF, const uint32_t* __restrict__ hB,
    const float* __restrict__ lw, const float* __restrict__ lb,
    float* __restrict__ outp)
{
    int w = (blockIdx.x * blockDim.x + threadIdx.x) >> 5;
    int lane = threadIdx.x & 31;
    if (w >= B_ * 2) return;
    int b = w >> 1, c = w & 1;
    float s = 0.f;
    for (int k = lane; k < 2 * H_; k += 32) {
        float xv = __uint_as_float((k < H_) ? hB[b * H_ + k] : hF[b * H_ + (k - H_)]);
        s += xv * lw[c * 2 * H_ + k];
    }
#pragma unroll
    for (int o = 16; o; o >>= 1) s += __shfl_xor_sync(0xffffffffu, s, o);
    if (lane == 0) outp[b * 2 + c] = s + lb[c];
}

// ---------------- launch ----------------------------------------------------
extern "C" void kernel_launch(void* const* d_in, const int* in_sizes, int n_in,
                              void* d_out, int out_size)
{
    const int*   tok      = (const int*)  d_in[0];
    const int*   lens     = (const int*)  d_in[1];
    const float* emb      = (const float*)d_in[2];
    const float* w_ih_l0f = (const float*)d_in[3];
    const float* w_hh_l0f = (const float*)d_in[4];
    const float* b_ih_l0f = (const float*)d_in[5];
    const float* b_hh_l0f = (const float*)d_in[6];
    const float* w_ih_l0b = (const float*)d_in[7];
    const float* w_hh_l0b = (const float*)d_in[8];
    const float* b_ih_l0b = (const float*)d_in[9];
    const float* b_hh_l0b = (const float*)d_in[10];
    const float* w_ih_l1f = (const float*)d_in[11];
    const float* w_hh_l1f = (const float*)d_in[12];
    const float* b_ih_l1f = (const float*)d_in[13];
    const float* b_hh_l1f = (const float*)d_in[14];
    const float* w_ih_l1b = (const float*)d_in[15];
    const float* w_hh_l1b = (const float*)d_in[16];
    const float* b_ih_l1b = (const float*)d_in[17];
    const float* b_hh_l1b = (const float*)d_in[18];
    const float* lin_w    = (const float*)d_in[19];
    const float* lin_b    = (const float*)d_in[20];

    uint32_t *x, *wA, *wB, *whF, *whB, *out0, *hF, *hB;
    float *xpF, *xpB;
    cudaGetSymbolAddress((void**)&x,    g_x);
    cudaGetSymbolAddress((void**)&wA,   g_wA);
    cudaGetSymbolAddress((void**)&wB,   g_wB);
    cudaGetSymbolAddress((void**)&whF,  g_whF);
    cudaGetSymbolAddress((void**)&whB,  g_whB);
    cudaGetSymbolAddress((void**)&xpF,  g_xpF);
    cudaGetSymbolAddress((void**)&xpB,  g_xpB);
    cudaGetSymbolAddress((void**)&out0, g_out0);
    cudaGetSymbolAddress((void**)&hF,   g_hF);
    cudaGetSymbolAddress((void**)&hB,   g_hB);

    cudaFuncSetAttribute(gemm_tf32, cudaFuncAttributeMaxDynamicSharedMemorySize, GEMM_SMEM);
    cudaFuncSetAttribute(lstm_layer_kernel, cudaFuncAttributeMaxDynamicSharedMemorySize, LSTM_SMEM);

    dim3 gg(G4_ / 128, M_ / 128);

    // 1. embedding gather -> tf32, K padded to 320
    gather_kernel<<<(M_ * EP_ + 255) / 256, 256>>>(tok, emb, x);

    // 2. convert layer-0 weights, then input projections (Ka = 320)
    conv_tf32<<<(G4_ * EP_ + 255) / 256, 256>>>(w_ih_l0f, wA, G4_, E_, EP_);
    conv_tf32<<<(G4_ * EP_ + 255) / 256, 256>>>(w_ih_l0b, wB, G4_, E_, EP_);
    conv_tf32_v4<<<(G4_ * H_ / 4 + 255) / 256, 256>>>((const float4*)w_hh_l0f, (uint4*)whF, G4_ * H_ / 4);
    conv_tf32_v4<<<(G4_ * H_ / 4 + 255) / 256, 256>>>((const float4*)w_hh_l0b, (uint4*)whB, G4_ * H_ / 4);
    gemm_tf32<<<gg, 256, GEMM_SMEM>>>(x, wA, b_ih_l0f, b_hh_l0f, xpF, EP_);
    gemm_tf32<<<gg, 256, GEMM_SMEM>>>(x, wB, b_ih_l0b, b_hh_l0b, xpB, EP_);

    // 3. layer-0 recurrence (writes [out_f || out_b] as tf32)
    lstm_layer_kernel<<<NCTA_REC, 256, LSTM_SMEM>>>(xpF, xpB, whF, whB, lens,
                                                    out0, hF, hB);

    // 4. convert layer-1 weights, then input projections (Ka = 2048)
    conv_tf32_v4<<<(G4_ * 2048 / 4 + 255) / 256, 256>>>((const float4*)w_ih_l1f, (uint4*)wA, G4_ * 2048 / 4);
    conv_tf32_v4<<<(G4_ * 2048 / 4 + 255) / 256, 256>>>((const float4*)w_ih_l1b, (uint4*)wB, G4_ * 2048 / 4);
    conv_tf32_v4<<<(G4_ * H_ / 4 + 255) / 256, 256>>>((const float4*)w_hh_l1f, (uint4*)whF, G4_ * H_ / 4);
    conv_tf32_v4<<<(G4_ * H_ / 4 + 255) / 256, 256>>>((const float4*)w_hh_l1b, (uint4*)whB, G4_ * H_ / 4);
    gemm_tf32<<<gg, 256, GEMM_SMEM>>>(out0, wA, b_ih_l1f, b_hh_l1f, xpF, 2 * H_);
    gemm_tf32<<<gg, 256, GEMM_SMEM>>>(out0, wB, b_ih_l1b, b_hh_l1b, xpB, 2 * H_);

    // 5. layer-1 recurrence (only final hiddens needed)
    lstm_layer_kernel<<<NCTA_REC, 256, LSTM_SMEM>>>(xpF, xpB, whF, whB, lens,
                                                    (uint32_t*)nullptr, hF, hB);

    // 6. head
    final_linear_kernel<<<8, 256>>>(hF, hB, lin_w, lin_b, (float*)d_out);
}

// round 4
// speedup vs baseline: 1.1345x; 1.1345x over previous
#include <cuda_runtime.h>
#include <cstdint>
#include <cstddef>

// Problem constants
#define B_   32
#define T_   512
#define E_   300
#define EP_  320              // padded embedding K (mult of 32)
#define H_   1024
#define G4_  4096             // 4*H
#define M_   (B_*T_)          // 16384 token rows
#define NCTA_REC 128

// ---------------- scratch (device globals; no allocation allowed) ----------
__device__ uint32_t g_x   [(size_t)M_ * EP_];      // embedded inputs (tf32)
__device__ uint32_t g_wA  [(size_t)G4_ * 2048];    // converted w_ih (dir f)
__device__ uint32_t g_wB  [(size_t)G4_ * 2048];    // converted w_ih (dir b)
__device__ uint32_t g_whF [(size_t)G4_ * H_];      // converted w_hh fwd
__device__ uint32_t g_whB [(size_t)G4_ * H_];      // converted w_hh bwd
__device__ float    g_xpF [(size_t)M_ * G4_];      // input projection fwd
__device__ float    g_xpB [(size_t)M_ * G4_];      // input projection bwd
__device__ uint32_t g_out0[(size_t)M_ * 2 * H_];   // layer0 output (tf32)
__device__ uint32_t g_hF  [B_ * H_];
__device__ uint32_t g_hB  [B_ * H_];
__device__ int      g_idx [M_];                    // compacted row -> b*T+t
__device__ int      g_Mc;                          // number of active rows
__device__ unsigned g_cnt [8 * 32];                // striped barrier counters
__device__ unsigned g_cntm;                        // master counter
__device__ volatile unsigned g_bar_gen;            // barrier generation (monotonic)

// ---------------- helpers ---------------------------------------------------
__device__ __forceinline__ uint32_t f2tf(float f) {
    uint32_t u;
    asm("cvt.rna.tf32.f32 %0, %1;" : "=r"(u) : "f"(f));
    return u;
}

__device__ __forceinline__ void mma8(float* c, const uint32_t* a, const uint32_t* b) {
    asm volatile(
        "mma.sync.aligned.m16n8k8.row.col.f32.tf32.tf32.f32 "
        "{%0,%1,%2,%3},{%4,%5,%6,%7},{%8,%9},{%0,%1,%2,%3};"
        : "+f"(c[0]), "+f"(c[1]), "+f"(c[2]), "+f"(c[3])
        : "r"(a[0]), "r"(a[1]), "r"(a[2]), "r"(a[3]), "r"(b[0]), "r"(b[1]));
}

__device__ __forceinline__ float sigmoidf_(float x) { return 1.f / (1.f + __expf(-x)); }

__device__ __forceinline__ uint32_t s2u(const void* p) {
    uint32_t r;
    asm("{ .reg .u64 t; cvta.to.shared.u64 t, %1; cvt.u32.u64 %0, t; }" : "=r"(r) : "l"(p));
    return r;
}
__device__ __forceinline__ void cp16(void* smem, const void* gmem) {
    asm volatile("cp.async.cg.shared.global [%0], [%1], 16;\n" :: "r"(s2u(smem)), "l"(gmem));
}
__device__ __forceinline__ void cp_commit() { asm volatile("cp.async.commit_group;"); }
template<int N> __device__ __forceinline__ void cp_wait() {
    asm volatile("cp.async.wait_group %0;" :: "n"(N));
}

// Striped grid barrier; grid is exactly NCTA_REC co-resident CTAs.
// Monotonic epochs: no counter resets, safe across kernel instances & replays.
__device__ __forceinline__ void grid_barrier(unsigned epoch) {
    __threadfence();
    __syncthreads();
    if (threadIdx.x == 0) {
        unsigned s = (blockIdx.x & 7) * 32;            // 8 stripes, 128B apart
        unsigned v = atomicAdd(&g_cnt[s], 1u) + 1u;
        if (v == 16u * epoch) {                        // last arrival in stripe
            unsigned a = atomicAdd(&g_cntm, 1u) + 1u;
            if (a == 8u * epoch) {                     // last stripe
                __threadfence();
                g_bar_gen = epoch;
            }
        }
        while (g_bar_gen < epoch) { }
    }
    __syncthreads();
}

// ---------------- kernel 0: build compacted row index ----------------------
__global__ __launch_bounds__(256) void build_idx_kernel(const int* __restrict__ lens)
{
    __shared__ int offs[B_];
    if (threadIdx.x == 0) {
        int s = 0;
        for (int b = 0; b < B_; b++) { offs[b] = s; s += lens[b]; }
        g_Mc = s;
    }
    __syncthreads();
    for (int b = 0; b < B_; b++) {
        int len = lens[b], o = offs[b];
        for (int t = threadIdx.x; t < len; t += 256)
            g_idx[o + t] = b * T_ + t;
    }
}

// ---------------- kernel 1: embedding gather (emit tf32, pad to 320) -------
__global__ __launch_bounds__(256) void gather_kernel(
    const int* __restrict__ tok, const float* __restrict__ emb, uint32_t* __restrict__ x)
{
    int i = blockIdx.x * 256 + threadIdx.x;
    if (i >= M_ * EP_) return;
    int bt = i / EP_;
    int e  = i - bt * EP_;
    x[i] = (e < E_) ? f2tf(emb[(size_t)tok[bt] * E_ + e]) : 0u;
}

// ---------------- kernel 1b: fp32 -> tf32 convert (with K padding) ---------
__global__ __launch_bounds__(256) void conv_tf32(
    const float* __restrict__ src, uint32_t* __restrict__ dst, int N, int K, int Kp)
{
    int i = blockIdx.x * 256 + threadIdx.x;
    if (i >= N * Kp) return;
    int n = i / Kp, k = i - n * Kp;
    dst[i] = (k < K) ? f2tf(src[(size_t)n * K + k]) : 0u;
}

// vectorized convert for K == Kp cases (elem count multiple of 4)
__global__ __launch_bounds__(256) void conv_tf32_v4(
    const float4* __restrict__ src, uint4* __restrict__ dst, int n4)
{
    int i = blockIdx.x * 256 + threadIdx.x;
    if (i >= n4) return;
    float4 v = src[i];
    uint4 o;
    o.x = f2tf(v.x); o.y = f2tf(v.y); o.z = f2tf(v.z); o.w = f2tf(v.w);
    dst[i] = o;
}

// ---------------- kernel 2: tf32 GEMM over compacted rows ------------------
// A rows gathered via g_idx, C rows scattered back via g_idx. CTAs whose
// m-tile lies entirely beyond g_Mc exit immediately.
#define GST 3
#define GEMM_SMEM (2 * GST * 128 * 36 * 4)
__global__ __launch_bounds__(256, 2) void gemm_tf32(
    const uint32_t* __restrict__ A, const uint32_t* __restrict__ Bw,
    const float* __restrict__ bias1, const float* __restrict__ bias2,
    float* __restrict__ C, int Ka)
{
    extern __shared__ char smraw[];
    uint32_t* As = (uint32_t*)smraw;              // GST * 128 * 36
    uint32_t* Bs = As + GST * 128 * 36;

    const int tid = threadIdx.x, warp = tid >> 5, lane = tid & 31;
    const int m0 = blockIdx.y * 128, n0 = blockIdx.x * 128;
    const int Mc = g_Mc;
    if (m0 >= Mc) return;
    const int wm = (warp >> 1) * 32, wn = (warp & 1) * 64;
    const uint32_t* Bg = Bw + (size_t)n0 * Ka;

    // gathered A-row base pointers (4 rows per thread, fixed across chunks)
    const uint32_t* Arow[4];
#pragma unroll
    for (int i = 0; i < 4; i++) {
        int glob = m0 + (tid >> 3) + 32 * i;
        int src  = g_idx[glob < Mc ? glob : Mc - 1];
        Arow[i] = A + (size_t)src * Ka + (tid & 7) * 4;
    }

    float acc[2][8][4];
#pragma unroll
    for (int i = 0; i < 2; i++)
#pragma unroll
        for (int j = 0; j < 8; j++)
#pragma unroll
            for (int k = 0; k < 4; k++) acc[i][j][k] = 0.f;

    auto issue = [&](int st, int kc) {
#pragma unroll
        for (int i = 0; i < 4; i++) {
            int row = (tid >> 3) + 32 * i, c4 = (tid & 7) * 4;
            cp16(As + st * 128 * 36 + row * 36 + c4, Arow[i] + kc);
            cp16(Bs + st * 128 * 36 + row * 36 + c4, Bg + (size_t)row * Ka + kc + c4);
        }
    };

    const int nc = Ka >> 5;
    issue(0, 0);  cp_commit();
    issue(1, 32); cp_commit();

    for (int c = 0; c < nc; c++) {
        if (c + 1 < nc) cp_wait<1>(); else cp_wait<0>();
        __syncthreads();
        if (c + 2 < nc) { issue((c + 2) % GST, (c + 2) * 32); cp_commit(); }

        const uint32_t* ab = As + (c % GST) * 128 * 36;
        const uint32_t* bb = Bs + (c % GST) * 128 * 36;
#pragma unroll
        for (int kk = 0; kk < 32; kk += 8) {
            int kq = kk + (lane & 3);
            uint32_t af[2][4], bf[8][2];
#pragma unroll
            for (int mt = 0; mt < 2; mt++) {
                int r = wm + mt * 16 + (lane >> 2);
                af[mt][0] = ab[r * 36 + kq];
                af[mt][1] = ab[(r + 8) * 36 + kq];
                af[mt][2] = ab[r * 36 + kq + 4];
                af[mt][3] = ab[(r + 8) * 36 + kq + 4];
            }
#pragma unroll
            for (int nt = 0; nt < 8; nt++) {
                int r = wn + nt * 8 + (lane >> 2);
                bf[nt][0] = bb[r * 36 + kq];
                bf[nt][1] = bb[r * 36 + kq + 4];
            }
#pragma unroll
            for (int mt = 0; mt < 2; mt++)
#pragma unroll
                for (int nt = 0; nt < 8; nt++)
                    mma8(acc[mt][nt], af[mt], bf[nt]);
        }
    }

    // epilogue: scatter rows through g_idx
    int rg[4]; const float* dummy;
    (void)dummy;
    size_t drow[4]; bool val[4];
#pragma unroll
    for (int mt = 0; mt < 2; mt++) {
        rg[mt * 2]     = m0 + wm + mt * 16 + (lane >> 2);
        rg[mt * 2 + 1] = rg[mt * 2] + 8;
    }
#pragma unroll
    for (int i = 0; i < 4; i++) {
        val[i]  = rg[i] < Mc;
        drow[i] = val[i] ? (size_t)g_idx[rg[i]] * G4_ : 0;
    }
#pragma unroll
    for (int mt = 0; mt < 2; mt++)
#pragma unroll
        for (int nt = 0; nt < 8; nt++) {
            int col = n0 + wn + nt * 8 + 2 * (lane & 3);
            float bv0 = bias1[col] + bias2[col];
            float bv1 = bias1[col + 1] + bias2[col + 1];
            if (val[mt * 2]) {
                C[drow[mt * 2] + col]     = acc[mt][nt][0] + bv0;
                C[drow[mt * 2] + col + 1] = acc[mt][nt][1] + bv1;
            }
            if (val[mt * 2 + 1]) {
                C[drow[mt * 2 + 1] + col]     = acc[mt][nt][2] + bv0;
                C[drow[mt * 2 + 1] + col + 1] = acc[mt][nt][3] + bv1;
            }
        }
}

// ---------------- kernel 3: persistent bi-LSTM layer -----------------------
// 128 CTAs: [0,64) fwd, [64,128) bwd. Each CTA owns 16 hidden cols (64 gate
// rows). First KPC k-chunks (of 64) of W_hh stay resident in SMEM; the rest
// and the h vector stream through 3-slot cp.async rings, distance-2 issue.
#define KPC    9                 // persistent k-chunks
#define WPSTR  580               // 9*64 + 4 pad (mod 32 == 4, conflict-free)
#define HSTR   68
#define WSTR   68
// GS aliases the H ring (dead after the chunk loop)
#define LSTM_SMEM ((64*WPSTR + 3*64*WSTR + 3*32*HSTR) * 4 + 512*4 + 512*4 + 128)
__global__ __launch_bounds__(256) void lstm_layer_kernel(
    const float* __restrict__ xpF, const float* __restrict__ xpB,
    const uint32_t* __restrict__ WhF, const uint32_t* __restrict__ WhB,
    const int* __restrict__ lengths,
    uint32_t* __restrict__ out,           // (B*T) x 2H tf32, or nullptr
    uint32_t* __restrict__ hF, uint32_t* __restrict__ hB)
{
    extern __shared__ char smraw[];
    uint32_t* WP  = (uint32_t*)smraw;            // [64][WPSTR] persistent W
    uint32_t* WSR = WP + 64 * WPSTR;             // [3][64][WSTR] streamed W ring
    uint32_t* HR  = WSR + 3 * 64 * WSTR;         // [3][32][HSTR] h ring
    float*    GS  = (float*)HR;                  // [32][64] gates (alias, post-loop)
    float*    CST = (float*)(HR + 3 * 32 * HSTR);// [512]
    float*    HST = CST + 512;                   // [512]
    int*      SLEN = (int*)(HST + 512);          // [32]

    const int tid = threadIdx.x, warp = tid >> 5, lane = tid & 31;
    const int cta = blockIdx.x;
    const int dir = cta >> 6;
    const int j0  = (cta & 63) * 16;
    const float*    xp   = dir ? xpB : xpF;
    const uint32_t* Wh   = dir ? WhB : WhF;
    uint32_t*       hdir = dir ? hB : hF;

    unsigned epoch = g_bar_gen;                  // monotonic base (pre-barrier)

    // init state + persistent W + lengths
    for (int p = tid; p < 512; p += 256) {
        int b = p >> 4, jl = p & 15;
        CST[p] = 0.f; HST[p] = 0.f;
        hdir[b * H_ + j0 + jl] = 0u;
    }
    if (tid < 32) SLEN[tid] = lengths[tid];
    for (int i = tid; i < 64 * (KPC * 64); i += 256) {
        int r = i / (KPC * 64), k = i - r * (KPC * 64);
        WP[r * WPSTR + k] = Wh[((size_t)((r >> 4) * H_ + j0 + (r & 15))) * H_ + k];
    }
    grid_barrier(++epoch);

    auto issueH = [&](int c) {
        uint32_t* dst = HR + (c % 3) * 32 * HSTR;
        const uint32_t* src = hdir + c * 64;
#pragma unroll
        for (int i = 0; i < 2; i++) {
            int seg = tid + i * 256;            // 512 segs of 16B
            int row = seg >> 4, c4 = (seg & 15) * 4;
            cp16(dst + row * HSTR + c4, src + row * H_ + c4);
        }
    };
    auto issueW = [&](int c) {
        uint32_t* dst = WSR + (c % 3) * 64 * WSTR;
#pragma unroll
        for (int i = 0; i < 4; i++) {
            int seg = tid + i * 256;            // 1024 segs
            int row = seg >> 4, c4 = (seg & 15) * 4;
            cp16(dst + row * WSTR + c4,
                 Wh + ((size_t)((row >> 4) * H_ + j0 + (row & 15))) * H_ + c * 64 + c4);
        }
    };

    for (int t = 0; t < T_; t++) {
        // prefetch this step's xp gate inputs into registers
        float xr[2][4];
#pragma unroll
        for (int p2 = 0; p2 < 2; p2++) {
            int p = tid + p2 * 256, b = p >> 4, jl = p & 15;
            int len = SLEN[b];
            int teff = dir ? ((t < len) ? (len - 1 - t) : 0) : t;
            const float* xb = xp + ((size_t)(b * T_ + teff)) * G4_ + j0 + jl;
            xr[p2][0] = __ldcs(xb);
            xr[p2][1] = __ldcs(xb + H_);
            xr[p2][2] = __ldcs(xb + 2 * H_);
            xr[p2][3] = __ldcs(xb + 3 * H_);
        }

        issueH(0); cp_commit();
        issueH(1); cp_commit();

        float acc[2][4];
#pragma unroll
        for (int mt = 0; mt < 2; mt++)
#pragma unroll
            for (int k = 0; k < 4; k++) acc[mt][k] = 0.f;

        for (int c = 0; c < 16; c++) {
            cp_wait<1>();
            __syncthreads();
            if (c + 2 < 16) {
                issueH(c + 2);
                if (c + 2 >= KPC) issueW(c + 2);
            }
            cp_commit();                         // unconditional: uniform groups

            const uint32_t* hb = HR + (c % 3) * 32 * HSTR;
            const uint32_t* wb; int wstr;
            if (c < KPC) { wb = WP + c * 64;               wstr = WPSTR; }
            else         { wb = WSR + (c % 3) * 64 * WSTR; wstr = WSTR; }
            const uint32_t* wrow = wb + (warp * 8 + (lane >> 2)) * wstr;
#pragma unroll
            for (int kk = 0; kk < 64; kk += 8) {
                int kq = kk + (lane & 3);
                uint32_t bf[2] = { wrow[kq], wrow[kq + 4] };
#pragma unroll
                for (int mt = 0; mt < 2; mt++) {
                    int r = mt * 16 + (lane >> 2);
                    uint32_t af[4] = { hb[r * HSTR + kq], hb[(r + 8) * HSTR + kq],
                                       hb[r * HSTR + kq + 4], hb[(r + 8) * HSTR + kq + 4] };
                    mma8(acc[mt], af, bf);
                }
            }
        }
        __syncthreads();      // protect GS alias of H ring

        // dump gate fragments (each warp owns its 8 columns of GS)
        {
            int rowb = lane >> 2, colb = warp * 8 + 2 * (lane & 3);
#pragma unroll
            for (int mt = 0; mt < 2; mt++) {
                GS[(mt * 16 + rowb) * 64 + colb]         = acc[mt][0];
                GS[(mt * 16 + rowb) * 64 + colb + 1]     = acc[mt][1];
                GS[(mt * 16 + rowb + 8) * 64 + colb]     = acc[mt][2];
                GS[(mt * 16 + rowb + 8) * 64 + colb + 1] = acc[mt][3];
            }
        }
        __syncthreads();

        // LSTM cell elementwise
#pragma unroll
        for (int p2 = 0; p2 < 2; p2++) {
            int p = tid + p2 * 256, b = p >> 4, jl = p & 15;
            int len = SLEN[b];
            bool msk = (t < len);
            float gi = GS[b * 64 + jl]      + xr[p2][0];
            float gf = GS[b * 64 + 16 + jl] + xr[p2][1];
            float gg = GS[b * 64 + 32 + jl] + xr[p2][2];
            float go = GS[b * 64 + 48 + jl] + xr[p2][3];
            if (msk) {
                float ii = sigmoidf_(gi), ff = sigmoidf_(gf);
                float gv = tanhf(gg),     oo = sigmoidf_(go);
                float cn = ff * CST[p] + ii * gv;
                float hn = oo * tanhf(cn);
                CST[p] = cn; HST[p] = hn;
                hdir[b * H_ + j0 + jl] = f2tf(hn);
            }
            if (out) {
                int pout = dir ? ((t < len) ? (len - 1 - t) : t) : t;
                out[((size_t)(b * T_ + pout)) * (2 * H_) + dir * H_ + j0 + jl] = f2tf(HST[p]);
            }
        }
        grid_barrier(++epoch);
    }
}

// ---------------- kernel 4: final linear  out = [h2b, h2f] @ lin_w^T + b ---
__global__ __launch_bounds__(256) void final_linear_kernel(
    const uint32_t* __restrict__ hF, const uint32_t* __restrict__ hB,
    const float* __restrict__ lw, const float* __restrict__ lb,
    float* __restrict__ outp)
{
    int w = (blockIdx.x * blockDim.x + threadIdx.x) >> 5;
    int lane = threadIdx.x & 31;
    if (w >= B_ * 2) return;
    int b = w >> 1, c = w & 1;
    float s = 0.f;
    for (int k = lane; k < 2 * H_; k += 32) {
        float xv = __uint_as_float((k < H_) ? hB[b * H_ + k] : hF[b * H_ + (k - H_)]);
        s += xv * lw[c * 2 * H_ + k];
    }
#pragma unroll
    for (int o = 16; o; o >>= 1) s += __shfl_xor_sync(0xffffffffu, s, o);
    if (lane == 0) outp[b * 2 + c] = s + lb[c];
}

// ---------------- launch ----------------------------------------------------
extern "C" void kernel_launch(void* const* d_in, const int* in_sizes, int n_in,
                              void* d_out, int out_size)
{
    const int*   tok      = (const int*)  d_in[0];
    const int*   lens     = (const int*)  d_in[1];
    const float* emb      = (const float*)d_in[2];
    const float* w_ih_l0f = (const float*)d_in[3];
    const float* w_hh_l0f = (const float*)d_in[4];
    const float* b_ih_l0f = (const float*)d_in[5];
    const float* b_hh_l0f = (const float*)d_in[6];
    const float* w_ih_l0b = (const float*)d_in[7];
    const float* w_hh_l0b = (const float*)d_in[8];
    const float* b_ih_l0b = (const float*)d_in[9];
    const float* b_hh_l0b = (const float*)d_in[10];
    const float* w_ih_l1f = (const float*)d_in[11];
    const float* w_hh_l1f = (const float*)d_in[12];
    const float* b_ih_l1f = (const float*)d_in[13];
    const float* b_hh_l1f = (const float*)d_in[14];
    const float* w_ih_l1b = (const float*)d_in[15];
    const float* w_hh_l1b = (const float*)d_in[16];
    const float* b_ih_l1b = (const float*)d_in[17];
    const float* b_hh_l1b = (const float*)d_in[18];
    const float* lin_w    = (const float*)d_in[19];
    const float* lin_b    = (const float*)d_in[20];

    uint32_t *x, *wA, *wB, *whF, *whB, *out0, *hF, *hB;
    float *xpF, *xpB;
    cudaGetSymbolAddress((void**)&x,    g_x);
    cudaGetSymbolAddress((void**)&wA,   g_wA);
    cudaGetSymbolAddress((void**)&wB,   g_wB);
    cudaGetSymbolAddress((void**)&whF,  g_whF);
    cudaGetSymbolAddress((void**)&whB,  g_whB);
    cudaGetSymbolAddress((void**)&xpF,  g_xpF);
    cudaGetSymbolAddress((void**)&xpB,  g_xpB);
    cudaGetSymbolAddress((void**)&out0, g_out0);
    cudaGetSymbolAddress((void**)&hF,   g_hF);
    cudaGetSymbolAddress((void**)&hB,   g_hB);

    cudaFuncSetAttribute(gemm_tf32, cudaFuncAttributeMaxDynamicSharedMemorySize, GEMM_SMEM);
    cudaFuncSetAttribute(lstm_layer_kernel, cudaFuncAttributeMaxDynamicSharedMemorySize, LSTM_SMEM);

    dim3 gg(G4_ / 128, M_ / 128);

    // 0. compacted row index (rows with t < len[b])
    build_idx_kernel<<<1, 256>>>(lens);

    // 1. embedding gather -> tf32, K padded to 320
    gather_kernel<<<(M_ * EP_ + 255) / 256, 256>>>(tok, emb, x);

    // 2. convert layer-0 weights, then input projections (Ka = 320)
    conv_tf32<<<(G4_ * EP_ + 255) / 256, 256>>>(w_ih_l0f, wA, G4_, E_, EP_);
    conv_tf32<<<(G4_ * EP_ + 255) / 256, 256>>>(w_ih_l0b, wB, G4_, E_, EP_);
    conv_tf32_v4<<<(G4_ * H_ / 4 + 255) / 256, 256>>>((const float4*)w_hh_l0f, (uint4*)whF, G4_ * H_ / 4);
    conv_tf32_v4<<<(G4_ * H_ / 4 + 255) / 256, 256>>>((const float4*)w_hh_l0b, (uint4*)whB, G4_ * H_ / 4);
    gemm_tf32<<<gg, 256, GEMM_SMEM>>>(x, wA, b_ih_l0f, b_hh_l0f, xpF, EP_);
    gemm_tf32<<<gg, 256, GEMM_SMEM>>>(x, wB, b_ih_l0b, b_hh_l0b, xpB, EP_);

    // 3. layer-0 recurrence (writes [out_f || out_b] as tf32)
    lstm_layer_kernel<<<NCTA_REC, 256, LSTM_SMEM>>>(xpF, xpB, whF, whB, lens,
                                                    out0, hF, hB);

    // 4. convert layer-1 weights, then input projections (Ka = 2048)
    conv_tf32_v4<<<(G4_ * 2048 / 4 + 255) / 256, 256>>>((const float4*)w_ih_l1f, (uint4*)wA, G4_ * 2048 / 4);
    conv_tf32_v4<<<(G4_ * 2048 / 4 + 255) / 256, 256>>>((const float4*)w_ih_l1b, (uint4*)wB, G4_ * 2048 / 4);
    conv_tf32_v4<<<(G4_ * H_ / 4 + 255) / 256, 256>>>((const float4*)w_hh_l1f, (uint4*)whF, G4_ * H_ / 4);
    conv_tf32_v4<<<(G4_ * H_ / 4 + 255) / 256, 256>>>((const float4*)w_hh_l1b, (uint4*)whB, G4_ * H_ / 4);
    gemm_tf32<<<gg, 256, GEMM_SMEM>>>(out0, wA, b_ih_l1f, b_hh_l1f, xpF, 2 * H_);
    gemm_tf32<<<gg, 256, GEMM_SMEM>>>(out0, wB, b_ih_l1b, b_hh_l1b, xpB, 2 * H_);

    // 5. layer-1 recurrence (only final hiddens needed)
    lstm_layer_kernel<<<NCTA_REC, 256, LSTM_SMEM>>>(xpF, xpB, whF, whB, lens,
                                                    (uint32_t*)nullptr, hF, hB);

    // 6. head
    final_linear_kernel<<<8, 256>>>(hF, hB, lin_w, lin_b, (float*)d_out);
}

// round 5
// speedup vs baseline: 2.1582x; 1.9024x over previous
#include <cuda_runtime.h>
#include <cuda_fp16.h>
#include <cstdint>
#include <cstddef>

// Problem constants
#define B_   32
#define T_   512
#define E_   300
#define EP_  320              // padded embedding K (mult of 32)
#define H_   1024
#define G4_  4096             // 4*H
#define M_   (B_*T_)          // 16384 token rows
#define NCTA_REC 128

// ---------------- scratch (device globals; no allocation allowed) ----------
__device__ uint32_t g_x   [(size_t)M_ * EP_];      // embedded inputs (tf32)
__device__ uint32_t g_wA  [(size_t)G4_ * 2048];    // converted w_ih (dir f)
__device__ uint32_t g_wB  [(size_t)G4_ * 2048];    // converted w_ih (dir b)
__device__ __half   g_whF [(size_t)G4_ * H_];      // converted w_hh fwd (fp16)
__device__ __half   g_whB [(size_t)G4_ * H_];      // converted w_hh bwd (fp16)
__device__ float    g_xpF [(size_t)M_ * G4_];      // input projection fwd
__device__ float    g_xpB [(size_t)M_ * G4_];      // input projection bwd
__device__ uint32_t g_out0[(size_t)M_ * 2 * H_];   // layer0 output (tf32)
__device__ __half   g_hF  [B_ * H_];
__device__ __half   g_hB  [B_ * H_];
__device__ int      g_idx [M_];                    // compacted row -> b*T+t
__device__ int      g_Mc;                          // number of active rows
__device__ unsigned g_cnt [8 * 32];                // striped barrier counters
__device__ unsigned g_cntm;                        // master counter
__device__ volatile unsigned g_bar_gen;            // barrier generation (monotonic)

// ---------------- helpers ---------------------------------------------------
__device__ __forceinline__ uint32_t f2tf(float f) {
    uint32_t u;
    asm("cvt.rna.tf32.f32 %0, %1;" : "=r"(u) : "f"(f));
    return u;
}

__device__ __forceinline__ void mma8(float* c, const uint32_t* a, const uint32_t* b) {
    asm volatile(
        "mma.sync.aligned.m16n8k8.row.col.f32.tf32.tf32.f32 "
        "{%0,%1,%2,%3},{%4,%5,%6,%7},{%8,%9},{%0,%1,%2,%3};"
        : "+f"(c[0]), "+f"(c[1]), "+f"(c[2]), "+f"(c[3])
        : "r"(a[0]), "r"(a[1]), "r"(a[2]), "r"(a[3]), "r"(b[0]), "r"(b[1]));
}

__device__ __forceinline__ void mma16(float* c, const uint32_t* a, const uint32_t* b) {
    asm volatile(
        "mma.sync.aligned.m16n8k16.row.col.f32.f16.f16.f32 "
        "{%0,%1,%2,%3},{%4,%5,%6,%7},{%8,%9},{%0,%1,%2,%3};"
        : "+f"(c[0]), "+f"(c[1]), "+f"(c[2]), "+f"(c[3])
        : "r"(a[0]), "r"(a[1]), "r"(a[2]), "r"(a[3]), "r"(b[0]), "r"(b[1]));
}

__device__ __forceinline__ void ldsm4(uint32_t* r, uint32_t addr) {
    asm volatile("ldmatrix.sync.aligned.m8n8.x4.shared.b16 {%0,%1,%2,%3}, [%4];"
        : "=r"(r[0]), "=r"(r[1]), "=r"(r[2]), "=r"(r[3]) : "r"(addr));
}

__device__ __forceinline__ float sigmoidf_(float x) { return 1.f / (1.f + __expf(-x)); }

__device__ __forceinline__ uint32_t s2u(const void* p) {
    uint32_t r;
    asm("{ .reg .u64 t; cvta.to.shared.u64 t, %1; cvt.u32.u64 %0, t; }" : "=r"(r) : "l"(p));
    return r;
}
__device__ __forceinline__ void cp16(void* smem, const void* gmem) {
    asm volatile("cp.async.cg.shared.global [%0], [%1], 16;\n" :: "r"(s2u(smem)), "l"(gmem));
}
__device__ __forceinline__ void cp_commit() { asm volatile("cp.async.commit_group;"); }
template<int N> __device__ __forceinline__ void cp_wait() {
    asm volatile("cp.async.wait_group %0;" :: "n"(N));
}

// Striped grid barrier; grid is exactly NCTA_REC co-resident CTAs.
// Monotonic epochs: no counter resets, safe across kernel instances & replays.
__device__ __forceinline__ void grid_barrier(unsigned epoch) {
    __threadfence();
    __syncthreads();
    if (threadIdx.x == 0) {
        unsigned s = (blockIdx.x & 7) * 32;            // 8 stripes, 128B apart
        unsigned v = atomicAdd(&g_cnt[s], 1u) + 1u;
        if (v == 16u * epoch) {                        // last arrival in stripe
            unsigned a = atomicAdd(&g_cntm, 1u) + 1u;
            if (a == 8u * epoch) {                     // last stripe
                __threadfence();
                g_bar_gen = epoch;
            }
        }
        while (g_bar_gen < epoch) { }
    }
    __syncthreads();
}

// ---------------- kernel 0: build compacted row index ----------------------
__global__ __launch_bounds__(256) void build_idx_kernel(const int* __restrict__ lens)
{
    __shared__ int offs[B_];
    if (threadIdx.x == 0) {
        int s = 0;
        for (int b = 0; b < B_; b++) { offs[b] = s; s += lens[b]; }
        g_Mc = s;
    }
    __syncthreads();
    for (int b = 0; b < B_; b++) {
        int len = lens[b], o = offs[b];
        for (int t = threadIdx.x; t < len; t += 256)
            g_idx[o + t] = b * T_ + t;
    }
}

// ---------------- kernel 1: embedding gather (emit tf32, pad to 320) -------
__global__ __launch_bounds__(256) void gather_kernel(
    const int* __restrict__ tok, const float* __restrict__ emb, uint32_t* __restrict__ x)
{
    int i = blockIdx.x * 256 + threadIdx.x;
    if (i >= M_ * EP_) return;
    int bt = i / EP_;
    int e  = i - bt * EP_;
    x[i] = (e < E_) ? f2tf(emb[(size_t)tok[bt] * E_ + e]) : 0u;
}

// ---------------- kernel 1b: fp32 -> tf32 convert (with K padding) ---------
__global__ __launch_bounds__(256) void conv_tf32(
    const float* __restrict__ src, uint32_t* __restrict__ dst, int N, int K, int Kp)
{
    int i = blockIdx.x * 256 + threadIdx.x;
    if (i >= N * Kp) return;
    int n = i / Kp, k = i - n * Kp;
    dst[i] = (k < K) ? f2tf(src[(size_t)n * K + k]) : 0u;
}

// vectorized tf32 convert (elem count multiple of 4)
__global__ __launch_bounds__(256) void conv_tf32_v4(
    const float4* __restrict__ src, uint4* __restrict__ dst, int n4)
{
    int i = blockIdx.x * 256 + threadIdx.x;
    if (i >= n4) return;
    float4 v = src[i];
    uint4 o;
    o.x = f2tf(v.x); o.y = f2tf(v.y); o.z = f2tf(v.z); o.w = f2tf(v.w);
    dst[i] = o;
}

// vectorized fp16 convert (elem count multiple of 4)
__global__ __launch_bounds__(256) void conv_f16_v4(
    const float4* __restrict__ src, __half2* __restrict__ dst, int n4)
{
    int i = blockIdx.x * 256 + threadIdx.x;
    if (i >= n4) return;
    float4 v = src[i];
    dst[2 * i]     = __floats2half2_rn(v.x, v.y);
    dst[2 * i + 1] = __floats2half2_rn(v.z, v.w);
}

// ---------------- kernel 2: tf32 GEMM over compacted rows ------------------
#define GST 3
#define GEMM_SMEM (2 * GST * 128 * 36 * 4)
__global__ __launch_bounds__(256, 2) void gemm_tf32(
    const uint32_t* __restrict__ A, const uint32_t* __restrict__ Bw,
    const float* __restrict__ bias1, const float* __restrict__ bias2,
    float* __restrict__ C, int Ka)
{
    extern __shared__ char smraw[];
    uint32_t* As = (uint32_t*)smraw;              // GST * 128 * 36
    uint32_t* Bs = As + GST * 128 * 36;

    const int tid = threadIdx.x, warp = tid >> 5, lane = tid & 31;
    const int m0 = blockIdx.y * 128, n0 = blockIdx.x * 128;
    const int Mc = g_Mc;
    if (m0 >= Mc) return;
    const int wm = (warp >> 1) * 32, wn = (warp & 1) * 64;
    const uint32_t* Bg = Bw + (size_t)n0 * Ka;

    const uint32_t* Arow[4];
#pragma unroll
    for (int i = 0; i < 4; i++) {
        int glob = m0 + (tid >> 3) + 32 * i;
        int src  = g_idx[glob < Mc ? glob : Mc - 1];
        Arow[i] = A + (size_t)src * Ka + (tid & 7) * 4;
    }

    float acc[2][8][4];
#pragma unroll
    for (int i = 0; i < 2; i++)
#pragma unroll
        for (int j = 0; j < 8; j++)
#pragma unroll
            for (int k = 0; k < 4; k++) acc[i][j][k] = 0.f;

    auto issue = [&](int st, int kc) {
#pragma unroll
        for (int i = 0; i < 4; i++) {
            int row = (tid >> 3) + 32 * i, c4 = (tid & 7) * 4;
            cp16(As + st * 128 * 36 + row * 36 + c4, Arow[i] + kc);
            cp16(Bs + st * 128 * 36 + row * 36 + c4, Bg + (size_t)row * Ka + kc + c4);
        }
    };

    const int nc = Ka >> 5;
    issue(0, 0);  cp_commit();
    issue(1, 32); cp_commit();

    for (int c = 0; c < nc; c++) {
        if (c + 1 < nc) cp_wait<1>(); else cp_wait<0>();
        __syncthreads();
        if (c + 2 < nc) { issue((c + 2) % GST, (c + 2) * 32); cp_commit(); }

        const uint32_t* ab = As + (c % GST) * 128 * 36;
        const uint32_t* bb = Bs + (c % GST) * 128 * 36;
#pragma unroll
        for (int kk = 0; kk < 32; kk += 8) {
            int kq = kk + (lane & 3);
            uint32_t af[2][4], bf[8][2];
#pragma unroll
            for (int mt = 0; mt < 2; mt++) {
                int r = wm + mt * 16 + (lane >> 2);
                af[mt][0] = ab[r * 36 + kq];
                af[mt][1] = ab[(r + 8) * 36 + kq];
                af[mt][2] = ab[r * 36 + kq + 4];
                af[mt][3] = ab[(r + 8) * 36 + kq + 4];
            }
#pragma unroll
            for (int nt = 0; nt < 8; nt++) {
                int r = wn + nt * 8 + (lane >> 2);
                bf[nt][0] = bb[r * 36 + kq];
                bf[nt][1] = bb[r * 36 + kq + 4];
            }
#pragma unroll
            for (int mt = 0; mt < 2; mt++)
#pragma unroll
                for (int nt = 0; nt < 8; nt++)
                    mma8(acc[mt][nt], af[mt], bf[nt]);
        }
    }

    int rg[4]; size_t drow[4]; bool val[4];
#pragma unroll
    for (int mt = 0; mt < 2; mt++) {
        rg[mt * 2]     = m0 + wm + mt * 16 + (lane >> 2);
        rg[mt * 2 + 1] = rg[mt * 2] + 8;
    }
#pragma unroll
    for (int i = 0; i < 4; i++) {
        val[i]  = rg[i] < Mc;
        drow[i] = val[i] ? (size_t)g_idx[rg[i]] * G4_ : 0;
    }
#pragma unroll
    for (int mt = 0; mt < 2; mt++)
#pragma unroll
        for (int nt = 0; nt < 8; nt++) {
            int col = n0 + wn + nt * 8 + 2 * (lane & 3);
            float bv0 = bias1[col] + bias2[col];
            float bv1 = bias1[col + 1] + bias2[col + 1];
            if (val[mt * 2]) {
                C[drow[mt * 2] + col]     = acc[mt][nt][0] + bv0;
                C[drow[mt * 2] + col + 1] = acc[mt][nt][1] + bv1;
            }
            if (val[mt * 2 + 1]) {
                C[drow[mt * 2 + 1] + col]     = acc[mt][nt][2] + bv0;
                C[drow[mt * 2 + 1] + col + 1] = acc[mt][nt][3] + bv1;
            }
        }
}

// ---------------- kernel 3: persistent bi-LSTM layer (fp16, resident W) ----
// 128 CTAs: [0,64) fwd, [64,128) bwd. Each CTA owns 16 hidden cols = 64 gate
// rows. Its full W_hh slice (64x1024 fp16 = 132 KB) is SMEM-resident. Per
// step: cp.async the 32x1024 fp16 h tile (64 KB), then warps 0-3 each compute
// an m32 x n16 slab of the 32x64 gate tile via mma.m16n8k16 with ldmatrix.
#define HSTRH 1032            // half-stride: 516 words, mod 32 == 4 -> conflict-free
#define LSTM_SMEM ((64 + 32) * HSTRH * 2 + 32*64*4 + 512*4 + 512*4 + 128)
__global__ __launch_bounds__(256) void lstm_layer_kernel(
    const float* __restrict__ xpF, const float* __restrict__ xpB,
    const __half* __restrict__ WhF, const __half* __restrict__ WhB,
    const int* __restrict__ lengths,
    uint32_t* __restrict__ out,           // (B*T) x 2H tf32, or nullptr
    __half* __restrict__ hF, __half* __restrict__ hB)
{
    extern __shared__ char smraw[];
    __half* WH  = (__half*)smraw;                 // [64][HSTRH] resident W
    __half* HT  = WH + 64 * HSTRH;                // [32][HSTRH] h tile
    float*  GS  = (float*)(HT + 32 * HSTRH);      // [32][64] gates
    float*  CST = GS + 32 * 64;                   // [512]
    float*  HST = CST + 512;                      // [512]
    int*    SLEN = (int*)(HST + 512);             // [32]

    const int tid = threadIdx.x, warp = tid >> 5, lane = tid & 31;
    const int cta = blockIdx.x;
    const int dir = cta >> 6;
    const int j0  = (cta & 63) * 16;
    const float*  xp   = dir ? xpB : xpF;
    const __half* Wh   = dir ? WhB : WhF;
    __half*       hdir = dir ? hB : hF;

    unsigned epoch = g_bar_gen;                   // monotonic base

    // init state + lengths
    for (int p = tid; p < 512; p += 256) {
        int b = p >> 4, jl = p & 15;
        CST[p] = 0.f; HST[p] = 0.f;
        hdir[b * H_ + j0 + jl] = __float2half(0.f);
    }
    if (tid < 32) SLEN[tid] = lengths[tid];
    // load resident W: 64 rows x 1024 halves = 8192 cp16
#pragma unroll
    for (int i = 0; i < 32; i++) {
        int seg = tid + i * 256;
        int r = seg >> 7, c8 = (seg & 127) * 8;
        cp16(WH + r * HSTRH + c8,
             Wh + ((size_t)((r >> 4) * H_ + j0 + (r & 15))) * H_ + c8);
    }
    cp_commit(); cp_wait<0>();
    grid_barrier(++epoch);

    const uint32_t HTu = s2u(HT);
    const uint32_t WHu = s2u(WH);
    // ldmatrix lane address components (A: m8n8.x4 over h tile; B: over W)
    const int rpA = (lane & 7) + ((lane >> 3) & 1) * 8;
    const int kpA = (lane >> 4) * 8;
    const uint32_t aB0 = HTu + ((0  + rpA) * HSTRH + kpA) * 2;
    const uint32_t aB1 = HTu + ((16 + rpA) * HSTRH + kpA) * 2;
    const int rpB = warp * 16 + (lane & 7) + (lane >> 4) * 8;
    const int kpB = ((lane >> 3) & 1) * 8;
    const uint32_t bB0 = WHu + (rpB * HSTRH + kpB) * 2;

    for (int t = 0; t < T_; t++) {
        // prefetch this step's xp gate inputs into registers
        float xr[2][4];
#pragma unroll
        for (int p2 = 0; p2 < 2; p2++) {
            int p = tid + p2 * 256, b = p >> 4, jl = p & 15;
            int len = SLEN[b];
            int teff = dir ? ((t < len) ? (len - 1 - t) : 0) : t;
            const float* xb = xp + ((size_t)(b * T_ + teff)) * G4_ + j0 + jl;
            xr[p2][0] = __ldcs(xb);
            xr[p2][1] = __ldcs(xb + H_);
            xr[p2][2] = __ldcs(xb + 2 * H_);
            xr[p2][3] = __ldcs(xb + 3 * H_);
        }

        // load full h tile: 32 rows x 1024 halves = 4096 cp16 (16/thread)
#pragma unroll
        for (int i = 0; i < 16; i++) {
            int seg = tid + i * 256;
            int row = seg >> 7, c8 = (seg & 127) * 8;
            cp16(HT + row * HSTRH + c8, hdir + row * H_ + c8);
        }
        cp_commit(); cp_wait<0>();
        __syncthreads();

        if (warp < 4) {
            float acc[2][2][4];
#pragma unroll
            for (int a = 0; a < 2; a++)
#pragma unroll
                for (int b = 0; b < 2; b++)
#pragma unroll
                    for (int k = 0; k < 4; k++) acc[a][b][k] = 0.f;

#pragma unroll 4
            for (int k = 0; k < H_; k += 16) {
                uint32_t a0[4], a1[4], bb[4];
                ldsm4(a0, aB0 + k * 2);
                ldsm4(a1, aB1 + k * 2);
                ldsm4(bb, bB0 + k * 2);
                mma16(acc[0][0], a0, bb);
                mma16(acc[0][1], a0, bb + 2);
                mma16(acc[1][0], a1, bb);
                mma16(acc[1][1], a1, bb + 2);
            }

            // dump gate fragments: warp owns cols [warp*16, warp*16+16)
            int rowb = lane >> 2, colb = warp * 16 + 2 * (lane & 3);
#pragma unroll
            for (int mt = 0; mt < 2; mt++)
#pragma unroll
                for (int nt = 0; nt < 2; nt++) {
                    GS[(mt * 16 + rowb) * 64 + colb + nt * 8]         = acc[mt][nt][0];
                    GS[(mt * 16 + rowb) * 64 + colb + nt * 8 + 1]     = acc[mt][nt][1];
                    GS[(mt * 16 + rowb + 8) * 64 + colb + nt * 8]     = acc[mt][nt][2];
                    GS[(mt * 16 + rowb + 8) * 64 + colb + nt * 8 + 1] = acc[mt][nt][3];
                }
        }
        __syncthreads();

        // LSTM cell elementwise
#pragma unroll
        for (int p2 = 0; p2 < 2; p2++) {
            int p = tid + p2 * 256, b = p >> 4, jl = p & 15;
            int len = SLEN[b];
            bool msk = (t < len);
            float gi = GS[b * 64 + jl]      + xr[p2][0];
            float gf = GS[b * 64 + 16 + jl] + xr[p2][1];
            float gg = GS[b * 64 + 32 + jl] + xr[p2][2];
            float go = GS[b * 64 + 48 + jl] + xr[p2][3];
            if (msk) {
                float ii = sigmoidf_(gi), ff = sigmoidf_(gf);
                float gv = tanhf(gg),     oo = sigmoidf_(go);
                float cn = ff * CST[p] + ii * gv;
                float hn = oo * tanhf(cn);
                CST[p] = cn; HST[p] = hn;
                hdir[b * H_ + j0 + jl] = __float2half_rn(hn);
            }
            if (out) {
                int pout = dir ? ((t < len) ? (len - 1 - t) : t) : t;
                out[((size_t)(b * T_ + pout)) * (2 * H_) + dir * H_ + j0 + jl] = f2tf(HST[p]);
            }
        }
        grid_barrier(++epoch);
    }
}

// ---------------- kernel 4: final linear  out = [h2b, h2f] @ lin_w^T + b ---
__global__ __launch_bounds__(256) void final_linear_kernel(
    const __half* __restrict__ hF, const __half* __restrict__ hB,
    const float* __restrict__ lw, const float* __restrict__ lb,
    float* __restrict__ outp)
{
    int w = (blockIdx.x * blockDim.x + threadIdx.x) >> 5;
    int lane = threadIdx.x & 31;
    if (w >= B_ * 2) return;
    int b = w >> 1, c = w & 1;
    float s = 0.f;
    for (int k = lane; k < 2 * H_; k += 32) {
        float xv = __half2float((k < H_) ? hB[b * H_ + k] : hF[b * H_ + (k - H_)]);
        s += xv * lw[c * 2 * H_ + k];
    }
#pragma unroll
    for (int o = 16; o; o >>= 1) s += __shfl_xor_sync(0xffffffffu, s, o);
    if (lane == 0) outp[b * 2 + c] = s + lb[c];
}

// ---------------- launch ----------------------------------------------------
extern "C" void kernel_launch(void* const* d_in, const int* in_sizes, int n_in,
                              void* d_out, int out_size)
{
    const int*   tok      = (const int*)  d_in[0];
    const int*   lens     = (const int*)  d_in[1];
    const float* emb      = (const float*)d_in[2];
    const float* w_ih_l0f = (const float*)d_in[3];
    const float* w_hh_l0f = (const float*)d_in[4];
    const float* b_ih_l0f = (const float*)d_in[5];
    const float* b_hh_l0f = (const float*)d_in[6];
    const float* w_ih_l0b = (const float*)d_in[7];
    const float* w_hh_l0b = (const float*)d_in[8];
    const float* b_ih_l0b = (const float*)d_in[9];
    const float* b_hh_l0b = (const float*)d_in[10];
    const float* w_ih_l1f = (const float*)d_in[11];
    const float* w_hh_l1f = (const float*)d_in[12];
    const float* b_ih_l1f = (const float*)d_in[13];
    const float* b_hh_l1f = (const float*)d_in[14];
    const float* w_ih_l1b = (const float*)d_in[15];
    const float* w_hh_l1b = (const float*)d_in[16];
    const float* b_ih_l1b = (const float*)d_in[17];
    const float* b_hh_l1b = (const float*)d_in[18];
    const float* lin_w    = (const float*)d_in[19];
    const float* lin_b    = (const float*)d_in[20];

    uint32_t *x, *wA, *wB, *out0;
    __half *whF, *whB, *hF, *hB;
    float *xpF, *xpB;
    cudaGetSymbolAddress((void**)&x,    g_x);
    cudaGetSymbolAddress((void**)&wA,   g_wA);
    cudaGetSymbolAddress((void**)&wB,   g_wB);
    cudaGetSymbolAddress((void**)&whF,  g_whF);
    cudaGetSymbolAddress((void**)&whB,  g_whB);
    cudaGetSymbolAddress((void**)&xpF,  g_xpF);
    cudaGetSymbolAddress((void**)&xpB,  g_xpB);
    cudaGetSymbolAddress((void**)&out0, g_out0);
    cudaGetSymbolAddress((void**)&hF,   g_hF);
    cudaGetSymbolAddress((void**)&hB,   g_hB);

    cudaFuncSetAttribute(gemm_tf32, cudaFuncAttributeMaxDynamicSharedMemorySize, GEMM_SMEM);
    cudaFuncSetAttribute(lstm_layer_kernel, cudaFuncAttributeMaxDynamicSharedMemorySize, LSTM_SMEM);

    dim3 gg(G4_ / 128, M_ / 128);

    // 0. compacted row index (rows with t < len[b])
    build_idx_kernel<<<1, 256>>>(lens);

    // 1. embedding gather -> tf32, K padded to 320
    gather_kernel<<<(M_ * EP_ + 255) / 256, 256>>>(tok, emb, x);

    // 2. convert layer-0 weights, then input projections (Ka = 320)
    conv_tf32<<<(G4_ * EP_ + 255) / 256, 256>>>(w_ih_l0f, wA, G4_, E_, EP_);
    conv_tf32<<<(G4_ * EP_ + 255) / 256, 256>>>(w_ih_l0b, wB, G4_, E_, EP_);
    conv_f16_v4<<<(G4_ * H_ / 4 + 255) / 256, 256>>>((const float4*)w_hh_l0f, (__half2*)whF, G4_ * H_ / 4);
    conv_f16_v4<<<(G4_ * H_ / 4 + 255) / 256, 256>>>((const float4*)w_hh_l0b, (__half2*)whB, G4_ * H_ / 4);
    gemm_tf32<<<gg, 256, GEMM_SMEM>>>(x, wA, b_ih_l0f, b_hh_l0f, xpF, EP_);
    gemm_tf32<<<gg, 256, GEMM_SMEM>>>(x, wB, b_ih_l0b, b_hh_l0b, xpB, EP_);

    // 3. layer-0 recurrence (writes [out_f || out_b] as tf32)
    lstm_layer_kernel<<<NCTA_REC, 256, LSTM_SMEM>>>(xpF, xpB, whF, whB, lens,
                                                    out0, hF, hB);

    // 4. convert layer-1 weights, then input projections (Ka = 2048)
    conv_tf32_v4<<<(G4_ * 2048 / 4 + 255) / 256, 256>>>((const float4*)w_ih_l1f, (uint4*)wA, G4_ * 2048 / 4);
    conv_tf32_v4<<<(G4_ * 2048 / 4 + 255) / 256, 256>>>((const float4*)w_ih_l1b, (uint4*)wB, G4_ * 2048 / 4);
    conv_f16_v4<<<(G4_ * H_ / 4 + 255) / 256, 256>>>((const float4*)w_hh_l1f, (__half2*)whF, G4_ * H_ / 4);
    conv_f16_v4<<<(G4_ * H_ / 4 + 255) / 256, 256>>>((const float4*)w_hh_l1b, (__half2*)whB, G4_ * H_ / 4);
    gemm_tf32<<<gg, 256, GEMM_SMEM>>>(out0, wA, b_ih_l1f, b_hh_l1f, xpF, 2 * H_);
    gemm_tf32<<<gg, 256, GEMM_SMEM>>>(out0, wB, b_ih_l1b, b_hh_l1b, xpB, 2 * H_);

    // 5. layer-1 recurrence (only final hiddens needed)
    lstm_layer_kernel<<<NCTA_REC, 256, LSTM_SMEM>>>(xpF, xpB, whF, whB, lens,
                                                    (uint32_t*)nullptr, hF, hB);

    // 6. head
    final_linear_kernel<<<8, 256>>>(hF, hB, lin_w, lin_b, (float*)d_out);
}

// round 6
// speedup vs baseline: 2.3656x; 1.0961x over previous
#include <cuda_runtime.h>
#include <cuda_fp16.h>
#include <cstdint>
#include <cstddef>

// Problem constants
#define B_   32
#define T_   512
#define E_   300
#define EP_  320              // padded embedding K (mult of 32)
#define H_   1024
#define G4_  4096             // 4*H
#define M_   (B_*T_)          // 16384 token rows
#define NCTA_REC 128

// ---------------- scratch (device globals; no allocation allowed) ----------
__device__ uint32_t g_x   [(size_t)M_ * EP_];      // embedded inputs (tf32)
__device__ uint32_t g_wA  [(size_t)G4_ * 2048];    // converted w_ih (dir f)
__device__ uint32_t g_wB  [(size_t)G4_ * 2048];    // converted w_ih (dir b)
__device__ __half   g_whF [(size_t)G4_ * H_];      // converted w_hh fwd (fp16)
__device__ __half   g_whB [(size_t)G4_ * H_];      // converted w_hh bwd (fp16)
__device__ float    g_xpF [(size_t)M_ * G4_];      // input projection fwd
__device__ float    g_xpB [(size_t)M_ * G4_];      // input projection bwd
__device__ uint32_t g_out0[(size_t)M_ * 2 * H_];   // layer0 output (tf32)
__device__ __half   g_hF  [B_ * H_];
__device__ __half   g_hB  [B_ * H_];
__device__ int      g_idx [M_];                    // compacted row -> b*T+t
__device__ int      g_Mc;                          // number of active rows
__device__ unsigned g_cnt [8 * 32];                // striped barrier counters
__device__ unsigned g_cntm;                        // master counter
__device__ volatile unsigned g_bar_gen;            // barrier generation (monotonic)

// ---------------- helpers ---------------------------------------------------
__device__ __forceinline__ uint32_t f2tf(float f) {
    uint32_t u;
    asm("cvt.rna.tf32.f32 %0, %1;" : "=r"(u) : "f"(f));
    return u;
}

__device__ __forceinline__ void mma8(float* c, const uint32_t* a, const uint32_t* b) {
    asm volatile(
        "mma.sync.aligned.m16n8k8.row.col.f32.tf32.tf32.f32 "
        "{%0,%1,%2,%3},{%4,%5,%6,%7},{%8,%9},{%0,%1,%2,%3};"
        : "+f"(c[0]), "+f"(c[1]), "+f"(c[2]), "+f"(c[3])
        : "r"(a[0]), "r"(a[1]), "r"(a[2]), "r"(a[3]), "r"(b[0]), "r"(b[1]));
}

__device__ __forceinline__ void mma16(float* c, const uint32_t* a, const uint32_t* b) {
    asm volatile(
        "mma.sync.aligned.m16n8k16.row.col.f32.f16.f16.f32 "
        "{%0,%1,%2,%3},{%4,%5,%6,%7},{%8,%9},{%0,%1,%2,%3};"
        : "+f"(c[0]), "+f"(c[1]), "+f"(c[2]), "+f"(c[3])
        : "r"(a[0]), "r"(a[1]), "r"(a[2]), "r"(a[3]), "r"(b[0]), "r"(b[1]));
}

__device__ __forceinline__ void ldsm4(uint32_t* r, uint32_t addr) {
    asm volatile("ldmatrix.sync.aligned.m8n8.x4.shared.b16 {%0,%1,%2,%3}, [%4];"
        : "=r"(r[0]), "=r"(r[1]), "=r"(r[2]), "=r"(r[3]) : "r"(addr));
}

__device__ __forceinline__ float sigmoidf_(float x) { return 1.f / (1.f + __expf(-x)); }

__device__ __forceinline__ uint32_t s2u(const void* p) {
    uint32_t r;
    asm("{ .reg .u64 t; cvta.to.shared.u64 t, %1; cvt.u32.u64 %0, t; }" : "=r"(r) : "l"(p));
    return r;
}
__device__ __forceinline__ void cp16(void* smem, const void* gmem) {
    asm volatile("cp.async.cg.shared.global [%0], [%1], 16;\n" :: "r"(s2u(smem)), "l"(gmem));
}
__device__ __forceinline__ void cp_commit() { asm volatile("cp.async.commit_group;"); }
template<int N> __device__ __forceinline__ void cp_wait() {
    asm volatile("cp.async.wait_group %0;" :: "n"(N));
}

// Striped grid barrier; grid is exactly NCTA_REC co-resident CTAs.
// Monotonic epochs: no counter resets, safe across kernel instances & replays.
__device__ __forceinline__ void grid_barrier(unsigned epoch) {
    __threadfence();
    __syncthreads();
    if (threadIdx.x == 0) {
        unsigned s = (blockIdx.x & 7) * 32;            // 8 stripes, 128B apart
        unsigned v = atomicAdd(&g_cnt[s], 1u) + 1u;
        if (v == 16u * epoch) {                        // last arrival in stripe
            unsigned a = atomicAdd(&g_cntm, 1u) + 1u;
            if (a == 8u * epoch) {                     // last stripe
                __threadfence();
                g_bar_gen = epoch;
            }
        }
        while (g_bar_gen < epoch) { }
    }
    __syncthreads();
}

// ---------------- kernel 0: build compacted row index ----------------------
__global__ __launch_bounds__(256) void build_idx_kernel(const int* __restrict__ lens)
{
    __shared__ int offs[B_];
    if (threadIdx.x == 0) {
        int s = 0;
        for (int b = 0; b < B_; b++) { offs[b] = s; s += lens[b]; }
        g_Mc = s;
    }
    __syncthreads();
    for (int b = 0; b < B_; b++) {
        int len = lens[b], o = offs[b];
        for (int t = threadIdx.x; t < len; t += 256)
            g_idx[o + t] = b * T_ + t;
    }
}

// ---------------- kernel 1: embedding gather (emit tf32, pad to 320) -------
__global__ __launch_bounds__(256) void gather_kernel(
    const int* __restrict__ tok, const float* __restrict__ emb, uint32_t* __restrict__ x)
{
    int i = blockIdx.x * 256 + threadIdx.x;
    if (i >= M_ * EP_) return;
    int bt = i / EP_;
    int e  = i - bt * EP_;
    x[i] = (e < E_) ? f2tf(emb[(size_t)tok[bt] * E_ + e]) : 0u;
}

// ---------------- kernel 1b: fp32 -> tf32 convert (with K padding) ---------
__global__ __launch_bounds__(256) void conv_tf32(
    const float* __restrict__ src, uint32_t* __restrict__ dst, int N, int K, int Kp)
{
    int i = blockIdx.x * 256 + threadIdx.x;
    if (i >= N * Kp) return;
    int n = i / Kp, k = i - n * Kp;
    dst[i] = (k < K) ? f2tf(src[(size_t)n * K + k]) : 0u;
}

// vectorized tf32 convert (elem count multiple of 4)
__global__ __launch_bounds__(256) void conv_tf32_v4(
    const float4* __restrict__ src, uint4* __restrict__ dst, int n4)
{
    int i = blockIdx.x * 256 + threadIdx.x;
    if (i >= n4) return;
    float4 v = src[i];
    uint4 o;
    o.x = f2tf(v.x); o.y = f2tf(v.y); o.z = f2tf(v.z); o.w = f2tf(v.w);
    dst[i] = o;
}

// vectorized fp16 convert (elem count multiple of 4)
__global__ __launch_bounds__(256) void conv_f16_v4(
    const float4* __restrict__ src, __half2* __restrict__ dst, int n4)
{
    int i = blockIdx.x * 256 + threadIdx.x;
    if (i >= n4) return;
    float4 v = src[i];
    dst[2 * i]     = __floats2half2_rn(v.x, v.y);
    dst[2 * i + 1] = __floats2half2_rn(v.z, v.w);
}

// ---------------- kernel 2: tf32 GEMM over compacted rows ------------------
#define GST 3
#define GEMM_SMEM (2 * GST * 128 * 36 * 4)
__global__ __launch_bounds__(256, 2) void gemm_tf32(
    const uint32_t* __restrict__ A, const uint32_t* __restrict__ Bw,
    const float* __restrict__ bias1, const float* __restrict__ bias2,
    float* __restrict__ C, int Ka)
{
    extern __shared__ char smraw[];
    uint32_t* As = (uint32_t*)smraw;              // GST * 128 * 36
    uint32_t* Bs = As + GST * 128 * 36;

    const int tid = threadIdx.x, warp = tid >> 5, lane = tid & 31;
    const int m0 = blockIdx.y * 128, n0 = blockIdx.x * 128;
    const int Mc = g_Mc;
    if (m0 >= Mc) return;
    const int wm = (warp >> 1) * 32, wn = (warp & 1) * 64;
    const uint32_t* Bg = Bw + (size_t)n0 * Ka;

    const uint32_t* Arow[4];
#pragma unroll
    for (int i = 0; i < 4; i++) {
        int glob = m0 + (tid >> 3) + 32 * i;
        int src  = g_idx[glob < Mc ? glob : Mc - 1];
        Arow[i] = A + (size_t)src * Ka + (tid & 7) * 4;
    }

    float acc[2][8][4];
#pragma unroll
    for (int i = 0; i < 2; i++)
#pragma unroll
        for (int j = 0; j < 8; j++)
#pragma unroll
            for (int k = 0; k < 4; k++) acc[i][j][k] = 0.f;

    auto issue = [&](int st, int kc) {
#pragma unroll
        for (int i = 0; i < 4; i++) {
            int row = (tid >> 3) + 32 * i, c4 = (tid & 7) * 4;
            cp16(As + st * 128 * 36 + row * 36 + c4, Arow[i] + kc);
            cp16(Bs + st * 128 * 36 + row * 36 + c4, Bg + (size_t)row * Ka + kc + c4);
        }
    };

    const int nc = Ka >> 5;
    issue(0, 0);  cp_commit();
    issue(1, 32); cp_commit();

    for (int c = 0; c < nc; c++) {
        if (c + 1 < nc) cp_wait<1>(); else cp_wait<0>();
        __syncthreads();
        if (c + 2 < nc) { issue((c + 2) % GST, (c + 2) * 32); cp_commit(); }

        const uint32_t* ab = As + (c % GST) * 128 * 36;
        const uint32_t* bb = Bs + (c % GST) * 128 * 36;
#pragma unroll
        for (int kk = 0; kk < 32; kk += 8) {
            int kq = kk + (lane & 3);
            uint32_t af[2][4], bf[8][2];
#pragma unroll
            for (int mt = 0; mt < 2; mt++) {
                int r = wm + mt * 16 + (lane >> 2);
                af[mt][0] = ab[r * 36 + kq];
                af[mt][1] = ab[(r + 8) * 36 + kq];
                af[mt][2] = ab[r * 36 + kq + 4];
                af[mt][3] = ab[(r + 8) * 36 + kq + 4];
            }
#pragma unroll
            for (int nt = 0; nt < 8; nt++) {
                int r = wn + nt * 8 + (lane >> 2);
                bf[nt][0] = bb[r * 36 + kq];
                bf[nt][1] = bb[r * 36 + kq + 4];
            }
#pragma unroll
            for (int mt = 0; mt < 2; mt++)
#pragma unroll
                for (int nt = 0; nt < 8; nt++)
                    mma8(acc[mt][nt], af[mt], bf[nt]);
        }
    }

    int rg[4]; size_t drow[4]; bool val[4];
#pragma unroll
    for (int mt = 0; mt < 2; mt++) {
        rg[mt * 2]     = m0 + wm + mt * 16 + (lane >> 2);
        rg[mt * 2 + 1] = rg[mt * 2] + 8;
    }
#pragma unroll
    for (int i = 0; i < 4; i++) {
        val[i]  = rg[i] < Mc;
        drow[i] = val[i] ? (size_t)g_idx[rg[i]] * G4_ : 0;
    }
#pragma unroll
    for (int mt = 0; mt < 2; mt++)
#pragma unroll
        for (int nt = 0; nt < 8; nt++) {
            int col = n0 + wn + nt * 8 + 2 * (lane & 3);
            float bv0 = bias1[col] + bias2[col];
            float bv1 = bias1[col + 1] + bias2[col + 1];
            if (val[mt * 2]) {
                C[drow[mt * 2] + col]     = acc[mt][nt][0] + bv0;
                C[drow[mt * 2] + col + 1] = acc[mt][nt][1] + bv1;
            }
            if (val[mt * 2 + 1]) {
                C[drow[mt * 2 + 1] + col]     = acc[mt][nt][2] + bv0;
                C[drow[mt * 2 + 1] + col + 1] = acc[mt][nt][3] + bv1;
            }
        }
}

// ---------------- kernel 3: persistent bi-LSTM layer (fp16, resident W) ----
// 128 CTAs: [0,64) fwd, [64,128) bwd. Each CTA owns 16 hidden cols = 64 gate
// rows; its W_hh slice (64x1024 fp16) is SMEM-resident. Split-K across all
// 8 warps: warps 0-3 k[0,512) -> GS0, warps 4-7 k[512,1024) -> GS1; cell
// sums. h tile streams in 4 column chunks (order c0,c2,c1,c3) overlapping
// phase-1 compute with phase-2 loads.
#define HSTRH 1032            // half-stride: 516 words, mod 32 == 4 -> conflict-free
#define LSTM_SMEM ((64 + 32) * HSTRH * 2 + 2*32*64*4 + 512*4 + 512*4 + 128)
__global__ __launch_bounds__(256) void lstm_layer_kernel(
    const float* __restrict__ xpF, const float* __restrict__ xpB,
    const __half* __restrict__ WhF, const __half* __restrict__ WhB,
    const int* __restrict__ lengths,
    uint32_t* __restrict__ out,           // (B*T) x 2H tf32, or nullptr
    __half* __restrict__ hF, __half* __restrict__ hB)
{
    extern __shared__ char smraw[];
    __half* WH  = (__half*)smraw;                 // [64][HSTRH] resident W
    __half* HT  = WH + 64 * HSTRH;                // [32][HSTRH] h tile
    float*  GS0 = (float*)(HT + 32 * HSTRH);      // [32][64] gates, k-half 0
    float*  GS1 = GS0 + 32 * 64;                  // [32][64] gates, k-half 1
    float*  CST = GS1 + 32 * 64;                  // [512]
    float*  HST = CST + 512;                      // [512]
    int*    SLEN = (int*)(HST + 512);             // [32]

    const int tid = threadIdx.x, warp = tid >> 5, lane = tid & 31;
    const int cta = blockIdx.x;
    const int dir = cta >> 6;
    const int j0  = (cta & 63) * 16;
    const float*  xp   = dir ? xpB : xpF;
    const __half* Wh   = dir ? WhB : WhF;
    __half*       hdir = dir ? hB : hF;

    unsigned epoch = g_bar_gen;                   // monotonic base

    // init state + lengths
    for (int p = tid; p < 512; p += 256) {
        int b = p >> 4, jl = p & 15;
        CST[p] = 0.f; HST[p] = 0.f;
        hdir[b * H_ + j0 + jl] = __float2half(0.f);
    }
    if (tid < 32) SLEN[tid] = lengths[tid];
    // load resident W: 64 rows x 1024 halves = 8192 cp16
#pragma unroll
    for (int i = 0; i < 32; i++) {
        int seg = tid + i * 256;
        int r = seg >> 7, c8 = (seg & 127) * 8;
        cp16(WH + r * HSTRH + c8,
             Wh + ((size_t)((r >> 4) * H_ + j0 + (r & 15))) * H_ + c8);
    }
    cp_commit(); cp_wait<0>();
    grid_barrier(++epoch);

    const uint32_t HTu = s2u(HT);
    const uint32_t WHu = s2u(WH);
    const int kh  = warp >> 2;                    // k-half (0/1)
    const int wq  = warp & 3;                     // n-quarter
    const int kb  = kh * 512;                     // k base (halves)
    // ldmatrix lane address components
    const int rpA = (lane & 7) + ((lane >> 3) & 1) * 8;
    const int kpA = (lane >> 4) * 8;
    const uint32_t aB0 = HTu + ((0  + rpA) * HSTRH + kpA + kb) * 2;
    const uint32_t aB1 = HTu + ((16 + rpA) * HSTRH + kpA + kb) * 2;
    const int rpB = wq * 16 + (lane & 7) + (lane >> 4) * 8;
    const int kpB = ((lane >> 3) & 1) * 8;
    const uint32_t bB0 = WHu + (rpB * HSTRH + kpB + kb) * 2;
    float* GSw = kh ? GS1 : GS0;

    // h chunk issuer: 256 columns starting at colbase (1024 cp16 / chunk)
    auto issueHC = [&](int colbase) {
#pragma unroll
        for (int i = 0; i < 4; i++) {
            int seg = tid + i * 256;
            int row = seg >> 5, c8 = (seg & 31) * 8;
            cp16(HT + row * HSTRH + colbase + c8, hdir + row * H_ + colbase + c8);
        }
    };

    for (int t = 0; t < T_; t++) {
        // prefetch this step's xp gate inputs into registers
        float xr[2][4];
#pragma unroll
        for (int p2 = 0; p2 < 2; p2++) {
            int p = tid + p2 * 256, b = p >> 4, jl = p & 15;
            int len = SLEN[b];
            int teff = dir ? ((t < len) ? (len - 1 - t) : 0) : t;
            const float* xb = xp + ((size_t)(b * T_ + teff)) * G4_ + j0 + jl;
            xr[p2][0] = __ldcs(xb);
            xr[p2][1] = __ldcs(xb + H_);
            xr[p2][2] = __ldcs(xb + 2 * H_);
            xr[p2][3] = __ldcs(xb + 3 * H_);
        }

        // issue h chunks: phase-1 chunks of both k-halves first
        issueHC(0);   cp_commit();    // cols [0,256)    - group0 phase1
        issueHC(512); cp_commit();    // cols [512,768)  - group1 phase1
        issueHC(256); cp_commit();    // cols [256,512)  - group0 phase2
        issueHC(768); cp_commit();    // cols [768,1024) - group1 phase2

        float acc[2][2][4];
#pragma unroll
        for (int a = 0; a < 2; a++)
#pragma unroll
            for (int b = 0; b < 2; b++)
#pragma unroll
                for (int k = 0; k < 4; k++) acc[a][b][k] = 0.f;

        // phase 1: first 256 k-columns of this warp's half
        cp_wait<2>();
        __syncthreads();
#pragma unroll 4
        for (int k = 0; k < 256; k += 16) {
            uint32_t a0[4], a1[4], bb[4];
            ldsm4(a0, aB0 + k * 2);
            ldsm4(a1, aB1 + k * 2);
            ldsm4(bb, bB0 + k * 2);
            mma16(acc[0][0], a0, bb);
            mma16(acc[0][1], a0, bb + 2);
            mma16(acc[1][0], a1, bb);
            mma16(acc[1][1], a1, bb + 2);
        }

        // phase 2: remaining 256 k-columns
        cp_wait<0>();
        __syncthreads();
#pragma unroll 4
        for (int k = 256; k < 512; k += 16) {
            uint32_t a0[4], a1[4], bb[4];
            ldsm4(a0, aB0 + k * 2);
            ldsm4(a1, aB1 + k * 2);
            ldsm4(bb, bB0 + k * 2);
            mma16(acc[0][0], a0, bb);
            mma16(acc[0][1], a0, bb + 2);
            mma16(acc[1][0], a1, bb);
            mma16(acc[1][1], a1, bb + 2);
        }

        // dump gate fragments: warp owns cols [wq*16, wq*16+16) of GSw
        {
            int rowb = lane >> 2, colb = wq * 16 + 2 * (lane & 3);
#pragma unroll
            for (int mt = 0; mt < 2; mt++)
#pragma unroll
                for (int nt = 0; nt < 2; nt++) {
                    GSw[(mt * 16 + rowb) * 64 + colb + nt * 8]         = acc[mt][nt][0];
                    GSw[(mt * 16 + rowb) * 64 + colb + nt * 8 + 1]     = acc[mt][nt][1];
                    GSw[(mt * 16 + rowb + 8) * 64 + colb + nt * 8]     = acc[mt][nt][2];
                    GSw[(mt * 16 + rowb + 8) * 64 + colb + nt * 8 + 1] = acc[mt][nt][3];
                }
        }
        __syncthreads();

        // LSTM cell elementwise (sum the two k-half partials)
#pragma unroll
        for (int p2 = 0; p2 < 2; p2++) {
            int p = tid + p2 * 256, b = p >> 4, jl = p & 15;
            int len = SLEN[b];
            bool msk = (t < len);
            float gi = GS0[b * 64 + jl]      + GS1[b * 64 + jl]      + xr[p2][0];
            float gf = GS0[b * 64 + 16 + jl] + GS1[b * 64 + 16 + jl] + xr[p2][1];
            float gg = GS0[b * 64 + 32 + jl] + GS1[b * 64 + 32 + jl] + xr[p2][2];
            float go = GS0[b * 64 + 48 + jl] + GS1[b * 64 + 48 + jl] + xr[p2][3];
            if (msk) {
                float ii = sigmoidf_(gi), ff = sigmoidf_(gf);
                float gv = tanhf(gg),     oo = sigmoidf_(go);
                float cn = ff * CST[p] + ii * gv;
                float hn = oo * tanhf(cn);
                CST[p] = cn; HST[p] = hn;
                hdir[b * H_ + j0 + jl] = __float2half_rn(hn);
            }
            if (out) {
                int pout = dir ? ((t < len) ? (len - 1 - t) : t) : t;
                out[((size_t)(b * T_ + pout)) * (2 * H_) + dir * H_ + j0 + jl] = f2tf(HST[p]);
            }
        }
        grid_barrier(++epoch);
    }
}

// ---------------- kernel 4: final linear  out = [h2b, h2f] @ lin_w^T + b ---
__global__ __launch_bounds__(256) void final_linear_kernel(
    const __half* __restrict__ hF, const __half* __restrict__ hB,
    const float* __restrict__ lw, const float* __restrict__ lb,
    float* __restrict__ outp)
{
    int w = (blockIdx.x * blockDim.x + threadIdx.x) >> 5;
    int lane = threadIdx.x & 31;
    if (w >= B_ * 2) return;
    int b = w >> 1, c = w & 1;
    float s = 0.f;
    for (int k = lane; k < 2 * H_; k += 32) {
        float xv = __half2float((k < H_) ? hB[b * H_ + k] : hF[b * H_ + (k - H_)]);
        s += xv * lw[c * 2 * H_ + k];
    }
#pragma unroll
    for (int o = 16; o; o >>= 1) s += __shfl_xor_sync(0xffffffffu, s, o);
    if (lane == 0) outp[b * 2 + c] = s + lb[c];
}

// ---------------- launch ----------------------------------------------------
extern "C" void kernel_launch(void* const* d_in, const int* in_sizes, int n_in,
                              void* d_out, int out_size)
{
    const int*   tok      = (const int*)  d_in[0];
    const int*   lens     = (const int*)  d_in[1];
    const float* emb      = (const float*)d_in[2];
    const float* w_ih_l0f = (const float*)d_in[3];
    const float* w_hh_l0f = (const float*)d_in[4];
    const float* b_ih_l0f = (const float*)d_in[5];
    const float* b_hh_l0f = (const float*)d_in[6];
    const float* w_ih_l0b = (const float*)d_in[7];
    const float* w_hh_l0b = (const float*)d_in[8];
    const float* b_ih_l0b = (const float*)d_in[9];
    const float* b_hh_l0b = (const float*)d_in[10];
    const float* w_ih_l1f = (const float*)d_in[11];
    const float* w_hh_l1f = (const float*)d_in[12];
    const float* b_ih_l1f = (const float*)d_in[13];
    const float* b_hh_l1f = (const float*)d_in[14];
    const float* w_ih_l1b = (const float*)d_in[15];
    const float* w_hh_l1b = (const float*)d_in[16];
    const float* b_ih_l1b = (const float*)d_in[17];
    const float* b_hh_l1b = (const float*)d_in[18];
    const float* lin_w    = (const float*)d_in[19];
    const float* lin_b    = (const float*)d_in[20];

    uint32_t *x, *wA, *wB, *out0;
    __half *whF, *whB, *hF, *hB;
    float *xpF, *xpB;
    cudaGetSymbolAddress((void**)&x,    g_x);
    cudaGetSymbolAddress((void**)&wA,   g_wA);
    cudaGetSymbolAddress((void**)&wB,   g_wB);
    cudaGetSymbolAddress((void**)&whF,  g_whF);
    cudaGetSymbolAddress((void**)&whB,  g_whB);
    cudaGetSymbolAddress((void**)&xpF,  g_xpF);
    cudaGetSymbolAddress((void**)&xpB,  g_xpB);
    cudaGetSymbolAddress((void**)&out0, g_out0);
    cudaGetSymbolAddress((void**)&hF,   g_hF);
    cudaGetSymbolAddress((void**)&hB,   g_hB);

    cudaFuncSetAttribute(gemm_tf32, cudaFuncAttributeMaxDynamicSharedMemorySize, GEMM_SMEM);
    cudaFuncSetAttribute(lstm_layer_kernel, cudaFuncAttributeMaxDynamicSharedMemorySize, LSTM_SMEM);

    dim3 gg(G4_ / 128, M_ / 128);

    // 0. compacted row index (rows with t < len[b])
    build_idx_kernel<<<1, 256>>>(lens);

    // 1. embedding gather -> tf32, K padded to 320
    gather_kernel<<<(M_ * EP_ + 255) / 256, 256>>>(tok, emb, x);

    // 2. convert layer-0 weights, then input projections (Ka = 320)
    conv_tf32<<<(G4_ * EP_ + 255) / 256, 256>>>(w_ih_l0f, wA, G4_, E_, EP_);
    conv_tf32<<<(G4_ * EP_ + 255) / 256, 256>>>(w_ih_l0b, wB, G4_, E_, EP_);
    conv_f16_v4<<<(G4_ * H_ / 4 + 255) / 256, 256>>>((const float4*)w_hh_l0f, (__half2*)whF, G4_ * H_ / 4);
    conv_f16_v4<<<(G4_ * H_ / 4 + 255) / 256, 256>>>((const float4*)w_hh_l0b, (__half2*)whB, G4_ * H_ / 4);
    gemm_tf32<<<gg, 256, GEMM_SMEM>>>(x, wA, b_ih_l0f, b_hh_l0f, xpF, EP_);
    gemm_tf32<<<gg, 256, GEMM_SMEM>>>(x, wB, b_ih_l0b, b_hh_l0b, xpB, EP_);

    // 3. layer-0 recurrence (writes [out_f || out_b] as tf32)
    lstm_layer_kernel<<<NCTA_REC, 256, LSTM_SMEM>>>(xpF, xpB, whF, whB, lens,
                                                    out0, hF, hB);

    // 4. convert layer-1 weights, then input projections (Ka = 2048)
    conv_tf32_v4<<<(G4_ * 2048 / 4 + 255) / 256, 256>>>((const float4*)w_ih_l1f, (uint4*)wA, G4_ * 2048 / 4);
    conv_tf32_v4<<<(G4_ * 2048 / 4 + 255) / 256, 256>>>((const float4*)w_ih_l1b, (uint4*)wB, G4_ * 2048 / 4);
    conv_f16_v4<<<(G4_ * H_ / 4 + 255) / 256, 256>>>((const float4*)w_hh_l1f, (__half2*)whF, G4_ * H_ / 4);
    conv_f16_v4<<<(G4_ * H_ / 4 + 255) / 256, 256>>>((const float4*)w_hh_l1b, (__half2*)whB, G4_ * H_ / 4);
    gemm_tf32<<<gg, 256, GEMM_SMEM>>>(out0, wA, b_ih_l1f, b_hh_l1f, xpF, 2 * H_);
    gemm_tf32<<<gg, 256, GEMM_SMEM>>>(out0, wB, b_ih_l1b, b_hh_l1b, xpB, 2 * H_);

    // 5. layer-1 recurrence (only final hiddens needed)
    lstm_layer_kernel<<<NCTA_REC, 256, LSTM_SMEM>>>(xpF, xpB, whF, whB, lens,
                                                    (uint32_t*)nullptr, hF, hB);

    // 6. head
    final_linear_kernel<<<8, 256>>>(hF, hB, lin_w, lin_b, (float*)d_out);
}

// round 7
// speedup vs baseline: 2.9008x; 1.2262x over previous
#include <cuda_runtime.h>
#include <cuda_fp16.h>
#include <cstdint>
#include <cstddef>

// Problem constants
#define B_   32
#define T_   512
#define E_   300
#define EP_  320              // padded embedding K (mult of 32)
#define H_   1024
#define G4_  4096             // 4*H
#define M_   (B_*T_)          // 16384 token rows
#define NCTA_REC 128

// ---------------- scratch (device globals; no allocation allowed) ----------
__device__ __half   g_x   [(size_t)M_ * EP_];      // embedded inputs (fp16)
__device__ __half   g_wA  [(size_t)G4_ * 2048];    // converted w_ih (dir f)
__device__ __half   g_wB  [(size_t)G4_ * 2048];    // converted w_ih (dir b)
__device__ __half   g_whF [(size_t)G4_ * H_];      // converted w_hh fwd (fp16)
__device__ __half   g_whB [(size_t)G4_ * H_];      // converted w_hh bwd (fp16)
__device__ float    g_xpF [(size_t)M_ * G4_];      // input projection fwd
__device__ float    g_xpB [(size_t)M_ * G4_];      // input projection bwd
__device__ __half   g_out0[(size_t)M_ * 2 * H_];   // layer0 output (fp16)
__device__ __half   g_hF  [B_ * H_];               // sorted-row layout
__device__ __half   g_hB  [B_ * H_];
__device__ int      g_idx [M_];                    // compacted row -> b*T+t
__device__ int      g_Mc;                          // number of active rows
__device__ int      g_perm[B_];                    // sorted row -> orig batch
__device__ int      g_nbt [T_];                    // active batches at step t
__device__ int      g_Tmax;                        // max length
__device__ unsigned g_cnt [8 * 32];                // striped barrier counters
__device__ unsigned g_cntm;                        // master counter
__device__ volatile unsigned g_bar_gen;            // barrier generation (monotonic)

// ---------------- helpers ---------------------------------------------------
__device__ __forceinline__ void mma16(float* c, const uint32_t* a, const uint32_t* b) {
    asm volatile(
        "mma.sync.aligned.m16n8k16.row.col.f32.f16.f16.f32 "
        "{%0,%1,%2,%3},{%4,%5,%6,%7},{%8,%9},{%0,%1,%2,%3};"
        : "+f"(c[0]), "+f"(c[1]), "+f"(c[2]), "+f"(c[3])
        : "r"(a[0]), "r"(a[1]), "r"(a[2]), "r"(a[3]), "r"(b[0]), "r"(b[1]));
}

__device__ __forceinline__ void ldsm4(uint32_t* r, uint32_t addr) {
    asm volatile("ldmatrix.sync.aligned.m8n8.x4.shared.b16 {%0,%1,%2,%3}, [%4];"
        : "=r"(r[0]), "=r"(r[1]), "=r"(r[2]), "=r"(r[3]) : "r"(addr));
}

__device__ __forceinline__ float sigmoidf_(float x) { return 1.f / (1.f + __expf(-x)); }

__device__ __forceinline__ uint32_t s2u(const void* p) {
    uint32_t r;
    asm("{ .reg .u64 t; cvta.to.shared.u64 t, %1; cvt.u32.u64 %0, t; }" : "=r"(r) : "l"(p));
    return r;
}
__device__ __forceinline__ void cp16(void* smem, const void* gmem) {
    asm volatile("cp.async.cg.shared.global [%0], [%1], 16;\n" :: "r"(s2u(smem)), "l"(gmem));
}
__device__ __forceinline__ void cp_commit() { asm volatile("cp.async.commit_group;"); }
template<int N> __device__ __forceinline__ void cp_wait() {
    asm volatile("cp.async.wait_group %0;" :: "n"(N));
}

// Striped grid barrier; grid is exactly NCTA_REC co-resident CTAs.
__device__ __forceinline__ void grid_barrier(unsigned epoch) {
    __threadfence();
    __syncthreads();
    if (threadIdx.x == 0) {
        unsigned s = (blockIdx.x & 7) * 32;            // 8 stripes, 128B apart
        unsigned v = atomicAdd(&g_cnt[s], 1u) + 1u;
        if (v == 16u * epoch) {
            unsigned a = atomicAdd(&g_cntm, 1u) + 1u;
            if (a == 8u * epoch) {
                __threadfence();
                g_bar_gen = epoch;
            }
        }
        while (g_bar_gen < epoch) { }
    }
    __syncthreads();
}

// ---------------- kernel 0: compacted index + sort + nbt -------------------
__global__ __launch_bounds__(256) void build_idx_kernel(const int* __restrict__ lens)
{
    __shared__ int sl[B_];
    __shared__ int offs[B_];
    int tid = threadIdx.x;
    if (tid < B_) sl[tid] = lens[tid];
    __syncthreads();
    if (tid == 0) {
        int s = 0;
        for (int b = 0; b < B_; b++) { offs[b] = s; s += sl[b]; }
        g_Mc = s;
        // deterministic selection sort, descending length (earliest idx wins ties)
        int pr[B_];
        for (int i = 0; i < B_; i++) pr[i] = i;
        for (int i = 0; i < B_; i++) {
            int best = i;
            for (int j = i + 1; j < B_; j++)
                if (sl[pr[j]] > sl[pr[best]]) best = j;
            int tmp = pr[i]; pr[i] = pr[best]; pr[best] = tmp;
        }
        int mx = 0;
        for (int i = 0; i < B_; i++) {
            g_perm[i] = pr[i];
            if (sl[i] > mx) mx = sl[i];
        }
        g_Tmax = mx;
    }
    __syncthreads();
    for (int t = tid; t < T_; t += 256) {
        int c = 0;
        for (int b = 0; b < B_; b++) c += (sl[b] > t);
        g_nbt[t] = c;
    }
    for (int b = 0; b < B_; b++) {
        int len = sl[b], o = offs[b];
        for (int t = tid; t < len; t += 256)
            g_idx[o + t] = b * T_ + t;
    }
}

// ---------------- kernel 1: embedding gather (emit fp16, pad to 320) -------
__global__ __launch_bounds__(256) void gather_kernel(
    const int* __restrict__ tok, const float* __restrict__ emb, __half* __restrict__ x)
{
    int i = blockIdx.x * 256 + threadIdx.x;
    if (i >= M_ * EP_) return;
    int bt = i / EP_;
    int e  = i - bt * EP_;
    x[i] = (e < E_) ? __float2half_rn(emb[(size_t)tok[bt] * E_ + e]) : __float2half(0.f);
}

// ---------------- kernel 1b: fp32 -> fp16 convert (with K padding) ---------
__global__ __launch_bounds__(256) void conv_f16_pad(
    const float* __restrict__ src, __half* __restrict__ dst, int N, int K, int Kp)
{
    int i = blockIdx.x * 256 + threadIdx.x;
    if (i >= N * Kp) return;
    int n = i / Kp, k = i - n * Kp;
    dst[i] = (k < K) ? __float2half_rn(src[(size_t)n * K + k]) : __half(0.f);
}

// vectorized fp16 convert (elem count multiple of 4)
__global__ __launch_bounds__(256) void conv_f16_v4(
    const float4* __restrict__ src, __half2* __restrict__ dst, int n4)
{
    int i = blockIdx.x * 256 + threadIdx.x;
    if (i >= n4) return;
    float4 v = src[i];
    dst[2 * i]     = __floats2half2_rn(v.x, v.y);
    dst[2 * i + 1] = __floats2half2_rn(v.z, v.w);
}

// ---------------- kernel 2: fp16 GEMM over compacted rows ------------------
// A: Mc x Ka fp16 (rows via g_idx), Bw: 4096 x Ka fp16, C: fp32 scatter.
// Tiles 128x128x32, 8 warps (4m x 2n), warp tile 32x64, mma.m16n8k16.
#define GST 3
#define ASTR 40
#define GEMM_SMEM (2 * GST * 128 * ASTR * 2)
__global__ __launch_bounds__(256, 2) void gemm_f16(
    const __half* __restrict__ A, const __half* __restrict__ Bw,
    const float* __restrict__ bias1, const float* __restrict__ bias2,
    float* __restrict__ C, int Ka)
{
    extern __shared__ char smraw[];
    __half* As = (__half*)smraw;                  // GST * 128 * ASTR
    __half* Bs = As + GST * 128 * ASTR;

    const int tid = threadIdx.x, warp = tid >> 5, lane = tid & 31;
    const int m0 = blockIdx.y * 128, n0 = blockIdx.x * 128;
    const int Mc = g_Mc;
    if (m0 >= Mc) return;
    const int wm = (warp >> 1) * 32, wn = (warp & 1) * 64;
    const __half* Bg = Bw + (size_t)n0 * Ka;

    // gathered A-row base pointers (2 rows per thread)
    const __half* Arow[2];
#pragma unroll
    for (int i = 0; i < 2; i++) {
        int glob = m0 + (tid >> 2) + 64 * i;
        int src  = g_idx[glob < Mc ? glob : Mc - 1];
        Arow[i] = A + (size_t)src * Ka + (tid & 3) * 8;
    }

    float acc[2][8][4];
#pragma unroll
    for (int i = 0; i < 2; i++)
#pragma unroll
        for (int j = 0; j < 8; j++)
#pragma unroll
            for (int k = 0; k < 4; k++) acc[i][j][k] = 0.f;

    auto issue = [&](int st, int kc) {
#pragma unroll
        for (int i = 0; i < 2; i++) {
            int row = (tid >> 2) + 64 * i, c8 = (tid & 3) * 8;
            cp16(As + st * 128 * ASTR + row * ASTR + c8, Arow[i] + kc);
            cp16(Bs + st * 128 * ASTR + row * ASTR + c8, Bg + (size_t)row * Ka + kc + c8);
        }
    };

    const int nc = Ka >> 5;
    issue(0, 0);  cp_commit();
    issue(1, 32); cp_commit();

    const uint32_t Au = s2u(As), Bu = s2u(Bs);
    const int rpA = (lane & 7) + ((lane >> 3) & 1) * 8;
    const int kpA = (lane >> 4) * 8;
    const int rpB = (lane & 7) + (lane >> 4) * 8;
    const int kpB = ((lane >> 3) & 1) * 8;

    for (int c = 0; c < nc; c++) {
        if (c + 1 < nc) cp_wait<1>(); else cp_wait<0>();
        __syncthreads();
        if (c + 2 < nc) { issue((c + 2) % GST, (c + 2) * 32); cp_commit(); }

        const uint32_t ab = Au + (c % GST) * 128 * ASTR * 2;
        const uint32_t bb = Bu + (c % GST) * 128 * ASTR * 2;
#pragma unroll
        for (int kk = 0; kk < 32; kk += 16) {
            uint32_t af[2][4], bf[4][4];
#pragma unroll
            for (int mt = 0; mt < 2; mt++)
                ldsm4(af[mt], ab + ((wm + mt * 16 + rpA) * ASTR + kpA + kk) * 2);
#pragma unroll
            for (int nt4 = 0; nt4 < 4; nt4++)
                ldsm4(bf[nt4], bb + ((wn + nt4 * 16 + rpB) * ASTR + kpB + kk) * 2);
#pragma unroll
            for (int mt = 0; mt < 2; mt++)
#pragma unroll
                for (int nt4 = 0; nt4 < 4; nt4++) {
                    mma16(acc[mt][nt4 * 2],     af[mt], bf[nt4]);
                    mma16(acc[mt][nt4 * 2 + 1], af[mt], bf[nt4] + 2);
                }
        }
    }

    int rg[4]; size_t drow[4]; bool val[4];
#pragma unroll
    for (int mt = 0; mt < 2; mt++) {
        rg[mt * 2]     = m0 + wm + mt * 16 + (lane >> 2);
        rg[mt * 2 + 1] = rg[mt * 2] + 8;
    }
#pragma unroll
    for (int i = 0; i < 4; i++) {
        val[i]  = rg[i] < Mc;
        drow[i] = val[i] ? (size_t)g_idx[rg[i]] * G4_ : 0;
    }
#pragma unroll
    for (int mt = 0; mt < 2; mt++)
#pragma unroll
        for (int nt = 0; nt < 8; nt++) {
            int col = n0 + wn + nt * 8 + 2 * (lane & 3);
            float bv0 = bias1[col] + bias2[col];
            float bv1 = bias1[col + 1] + bias2[col + 1];
            if (val[mt * 2]) {
                C[drow[mt * 2] + col]     = acc[mt][nt][0] + bv0;
                C[drow[mt * 2] + col + 1] = acc[mt][nt][1] + bv1;
            }
            if (val[mt * 2 + 1]) {
                C[drow[mt * 2 + 1] + col]     = acc[mt][nt][2] + bv0;
                C[drow[mt * 2 + 1] + col + 1] = acc[mt][nt][3] + bv1;
            }
        }
}

// ---------------- kernel 3: persistent bi-LSTM layer (fp16, resident W) ----
// Batches sorted by descending length (rows = sorted order). At step t only
// nb = g_nbt[t] rows are live: load 16 h rows + half MMA when nb <= 16, skip
// cell/out entirely for dead rows. Loop runs to Tmax = max(len).
#define HSTRH 1032            // half-stride: 516 words, mod 32 == 4 -> conflict-free
#define LSTM_SMEM ((64 + 32) * HSTRH * 2 + 2*32*64*4 + 512*4 + 512*4 + T_*4 + 64*4 + 128)
__global__ __launch_bounds__(256) void lstm_layer_kernel(
    const float* __restrict__ xpF, const float* __restrict__ xpB,
    const __half* __restrict__ WhF, const __half* __restrict__ WhB,
    const int* __restrict__ lengths,
    __half* __restrict__ out,             // (B*T) x 2H fp16, or nullptr
    __half* __restrict__ hF, __half* __restrict__ hB)
{
    extern __shared__ char smraw[];
    __half* WH  = (__half*)smraw;                 // [64][HSTRH] resident W
    __half* HT  = WH + 64 * HSTRH;                // [32][HSTRH] h tile
    float*  GS0 = (float*)(HT + 32 * HSTRH);      // [32][64] gates, k-half 0
    float*  GS1 = GS0 + 32 * 64;                  // [32][64] gates, k-half 1
    float*  CST = GS1 + 32 * 64;                  // [512]
    float*  HST = CST + 512;                      // [512]
    int*    NBT = (int*)(HST + 512);              // [T_]
    int*    SLEN = NBT + T_;                      // [32] sorted lengths
    int*    SPRM = SLEN + 32;                     // [32] sorted -> orig batch

    const int tid = threadIdx.x, warp = tid >> 5, lane = tid & 31;
    const int cta = blockIdx.x;
    const int dir = cta >> 6;
    const int j0  = (cta & 63) * 16;
    const float*  xp   = dir ? xpB : xpF;
    const __half* Wh   = dir ? WhB : WhF;
    __half*       hdir = dir ? hB : hF;

    unsigned epoch = g_bar_gen;                   // monotonic base

    // init state + sorted lengths/perm + nbt table
    for (int p = tid; p < 512; p += 256) {
        int b = p >> 4, jl = p & 15;
        CST[p] = 0.f; HST[p] = 0.f;
        hdir[b * H_ + j0 + jl] = __float2half(0.f);
    }
    if (tid < 32) {
        int pb = g_perm[tid];
        SPRM[tid] = pb;
        SLEN[tid] = lengths[pb];
    }
    for (int i = tid; i < T_; i += 256) NBT[i] = g_nbt[i];
    const int Tmax = g_Tmax;
    // load resident W: 64 rows x 1024 halves = 8192 cp16
#pragma unroll
    for (int i = 0; i < 32; i++) {
        int seg = tid + i * 256;
        int r = seg >> 7, c8 = (seg & 127) * 8;
        cp16(WH + r * HSTRH + c8,
             Wh + ((size_t)((r >> 4) * H_ + j0 + (r & 15))) * H_ + c8);
    }
    cp_commit(); cp_wait<0>();
    grid_barrier(++epoch);

    const uint32_t HTu = s2u(HT);
    const uint32_t WHu = s2u(WH);
    const int kh  = warp >> 2;                    // k-half (0/1)
    const int wq  = warp & 3;                     // n-quarter
    const int kb  = kh * 512;                     // k base (halves)
    const int rpA = (lane & 7) + ((lane >> 3) & 1) * 8;
    const int kpA = (lane >> 4) * 8;
    const uint32_t aB0 = HTu + ((0  + rpA) * HSTRH + kpA + kb) * 2;
    const uint32_t aB1 = HTu + ((16 + rpA) * HSTRH + kpA + kb) * 2;
    const int rpB = wq * 16 + (lane & 7) + (lane >> 4) * 8;
    const int kpB = ((lane >> 3) & 1) * 8;
    const uint32_t bB0 = WHu + (rpB * HSTRH + kpB + kb) * 2;
    float* GSw = kh ? GS1 : GS0;

    // h chunk issuer: 256 cols from colbase, nrow8*8 rows
    auto issueHC = [&](int colbase, int nrow8) {
        for (int i = 0; i < nrow8; i++) {
            int seg = tid + i * 256;
            int row = seg >> 5, c8 = (seg & 31) * 8;
            cp16(HT + row * HSTRH + colbase + c8, hdir + row * H_ + colbase + c8);
        }
    };

    for (int t = 0; t < Tmax; t++) {
        const int nb = NBT[t];
        const bool full = nb > 16;
        const int nrow8 = full ? 4 : 2;

        // prefetch this step's xp gate inputs (live rows only)
        float xr[2][4];
        bool  act[2];
#pragma unroll
        for (int p2 = 0; p2 < 2; p2++) {
            int p = tid + p2 * 256, b = p >> 4, jl = p & 15;
            act[p2] = (t < SLEN[b]);
            if (act[p2]) {
                int pb = SPRM[b];
                int teff = dir ? (SLEN[b] - 1 - t) : t;
                const float* xb = xp + ((size_t)(pb * T_ + teff)) * G4_ + j0 + jl;
                xr[p2][0] = __ldcs(xb);
                xr[p2][1] = __ldcs(xb + H_);
                xr[p2][2] = __ldcs(xb + 2 * H_);
                xr[p2][3] = __ldcs(xb + 3 * H_);
            }
        }

        // issue h chunks: phase-1 chunks of both k-halves first
        issueHC(0,   nrow8); cp_commit();
        issueHC(512, nrow8); cp_commit();
        issueHC(256, nrow8); cp_commit();
        issueHC(768, nrow8); cp_commit();

        float acc[2][2][4];
#pragma unroll
        for (int a = 0; a < 2; a++)
#pragma unroll
            for (int b = 0; b < 2; b++)
#pragma unroll
                for (int k = 0; k < 4; k++) acc[a][b][k] = 0.f;

        // phase 1
        cp_wait<2>();
        __syncthreads();
#pragma unroll 4
        for (int k = 0; k < 256; k += 16) {
            uint32_t a0[4], bb[4];
            ldsm4(a0, aB0 + k * 2);
            ldsm4(bb, bB0 + k * 2);
            mma16(acc[0][0], a0, bb);
            mma16(acc[0][1], a0, bb + 2);
            if (full) {
                uint32_t a1[4];
                ldsm4(a1, aB1 + k * 2);
                mma16(acc[1][0], a1, bb);
                mma16(acc[1][1], a1, bb + 2);
            }
        }

        // phase 2
        cp_wait<0>();
        __syncthreads();
#pragma unroll 4
        for (int k = 256; k < 512; k += 16) {
            uint32_t a0[4], bb[4];
            ldsm4(a0, aB0 + k * 2);
            ldsm4(bb, bB0 + k * 2);
            mma16(acc[0][0], a0, bb);
            mma16(acc[0][1], a0, bb + 2);
            if (full) {
                uint32_t a1[4];
                ldsm4(a1, aB1 + k * 2);
                mma16(acc[1][0], a1, bb);
                mma16(acc[1][1], a1, bb + 2);
            }
        }

        // dump gate fragments
        {
            int rowb = lane >> 2, colb = wq * 16 + 2 * (lane & 3);
#pragma unroll
            for (int nt = 0; nt < 2; nt++) {
                GSw[rowb * 64 + colb + nt * 8]           = acc[0][nt][0];
                GSw[rowb * 64 + colb + nt * 8 + 1]       = acc[0][nt][1];
                GSw[(rowb + 8) * 64 + colb + nt * 8]     = acc[0][nt][2];
                GSw[(rowb + 8) * 64 + colb + nt * 8 + 1] = acc[0][nt][3];
            }
            if (full) {
#pragma unroll
                for (int nt = 0; nt < 2; nt++) {
                    GSw[(16 + rowb) * 64 + colb + nt * 8]     = acc[1][nt][0];
                    GSw[(16 + rowb) * 64 + colb + nt * 8 + 1] = acc[1][nt][1];
                    GSw[(24 + rowb) * 64 + colb + nt * 8]     = acc[1][nt][2];
                    GSw[(24 + rowb) * 64 + colb + nt * 8 + 1] = acc[1][nt][3];
                }
            }
        }
        __syncthreads();

        // LSTM cell elementwise (live rows only)
#pragma unroll
        for (int p2 = 0; p2 < 2; p2++) {
            if (!act[p2]) continue;
            int p = tid + p2 * 256, b = p >> 4, jl = p & 15;
            float gi = GS0[b * 64 + jl]      + GS1[b * 64 + jl]      + xr[p2][0];
            float gf = GS0[b * 64 + 16 + jl] + GS1[b * 64 + 16 + jl] + xr[p2][1];
            float gg = GS0[b * 64 + 32 + jl] + GS1[b * 64 + 32 + jl] + xr[p2][2];
            float go = GS0[b * 64 + 48 + jl] + GS1[b * 64 + 48 + jl] + xr[p2][3];
            float ii = sigmoidf_(gi), ff = sigmoidf_(gf);
            float gv = tanhf(gg),     oo = sigmoidf_(go);
            float cn = ff * CST[p] + ii * gv;
            float hn = oo * tanhf(cn);
            CST[p] = cn; HST[p] = hn;
            __half hh = __float2half_rn(hn);
            hdir[b * H_ + j0 + jl] = hh;
            if (out) {
                int pb = SPRM[b];
                int pout = dir ? (SLEN[b] - 1 - t) : t;
                out[((size_t)(pb * T_ + pout)) * (2 * H_) + dir * H_ + j0 + jl] = hh;
            }
        }
        grid_barrier(++epoch);
    }
}

// ---------------- kernel 4: final linear  out = [h2b, h2f] @ lin_w^T + b ---
__global__ __launch_bounds__(256) void final_linear_kernel(
    const __half* __restrict__ hF, const __half* __restrict__ hB,
    const float* __restrict__ lw, const float* __restrict__ lb,
    float* __restrict__ outp)
{
    int w = (blockIdx.x * blockDim.x + threadIdx.x) >> 5;
    int lane = threadIdx.x & 31;
    if (w >= B_ * 2) return;
    int b = w >> 1, c = w & 1;          // b = sorted row
    int pb = g_perm[b];                  // original batch
    float s = 0.f;
    for (int k = lane; k < 2 * H_; k += 32) {
        float xv = __half2float((k < H_) ? hB[b * H_ + k] : hF[b * H_ + (k - H_)]);
        s += xv * lw[c * 2 * H_ + k];
    }
#pragma unroll
    for (int o = 16; o; o >>= 1) s += __shfl_xor_sync(0xffffffffu, s, o);
    if (lane == 0) outp[pb * 2 + c] = s + lb[c];
}

// ---------------- launch ----------------------------------------------------
extern "C" void kernel_launch(void* const* d_in, const int* in_sizes, int n_in,
                              void* d_out, int out_size)
{
    const int*   tok      = (const int*)  d_in[0];
    const int*   lens     = (const int*)  d_in[1];
    const float* emb      = (const float*)d_in[2];
    const float* w_ih_l0f = (const float*)d_in[3];
    const float* w_hh_l0f = (const float*)d_in[4];
    const float* b_ih_l0f = (const float*)d_in[5];
    const float* b_hh_l0f = (const float*)d_in[6];
    const float* w_ih_l0b = (const float*)d_in[7];
    const float* w_hh_l0b = (const float*)d_in[8];
    const float* b_ih_l0b = (const float*)d_in[9];
    const float* b_hh_l0b = (const float*)d_in[10];
    const float* w_ih_l1f = (const float*)d_in[11];
    const float* w_hh_l1f = (const float*)d_in[12];
    const float* b_ih_l1f = (const float*)d_in[13];
    const float* b_hh_l1f = (const float*)d_in[14];
    const float* w_ih_l1b = (const float*)d_in[15];
    const float* w_hh_l1b = (const float*)d_in[16];
    const float* b_ih_l1b = (const float*)d_in[17];
    const float* b_hh_l1b = (const float*)d_in[18];
    const float* lin_w    = (const float*)d_in[19];
    const float* lin_b    = (const float*)d_in[20];

    __half *x, *wA, *wB, *whF, *whB, *out0, *hF, *hB;
    float *xpF, *xpB;
    cudaGetSymbolAddress((void**)&x,    g_x);
    cudaGetSymbolAddress((void**)&wA,   g_wA);
    cudaGetSymbolAddress((void**)&wB,   g_wB);
    cudaGetSymbolAddress((void**)&whF,  g_whF);
    cudaGetSymbolAddress((void**)&whB,  g_whB);
    cudaGetSymbolAddress((void**)&xpF,  g_xpF);
    cudaGetSymbolAddress((void**)&xpB,  g_xpB);
    cudaGetSymbolAddress((void**)&out0, g_out0);
    cudaGetSymbolAddress((void**)&hF,   g_hF);
    cudaGetSymbolAddress((void**)&hB,   g_hB);

    cudaFuncSetAttribute(gemm_f16, cudaFuncAttributeMaxDynamicSharedMemorySize, GEMM_SMEM);
    cudaFuncSetAttribute(lstm_layer_kernel, cudaFuncAttributeMaxDynamicSharedMemorySize, LSTM_SMEM);

    dim3 gg(G4_ / 128, M_ / 128);

    // 0. compacted row index + sorted perm + nbt
    build_idx_kernel<<<1, 256>>>(lens);

    // 1. embedding gather -> fp16, K padded to 320
    gather_kernel<<<(M_ * EP_ + 255) / 256, 256>>>(tok, emb, x);

    // 2. convert layer-0 weights, then input projections (Ka = 320)
    conv_f16_pad<<<(G4_ * EP_ + 255) / 256, 256>>>(w_ih_l0f, wA, G4_, E_, EP_);
    conv_f16_pad<<<(G4_ * EP_ + 255) / 256, 256>>>(w_ih_l0b, wB, G4_, E_, EP_);
    conv_f16_v4<<<(G4_ * H_ / 4 + 255) / 256, 256>>>((const float4*)w_hh_l0f, (__half2*)whF, G4_ * H_ / 4);
    conv_f16_v4<<<(G4_ * H_ / 4 + 255) / 256, 256>>>((const float4*)w_hh_l0b, (__half2*)whB, G4_ * H_ / 4);
    gemm_f16<<<gg, 256, GEMM_SMEM>>>(x, wA, b_ih_l0f, b_hh_l0f, xpF, EP_);
    gemm_f16<<<gg, 256, GEMM_SMEM>>>(x, wB, b_ih_l0b, b_hh_l0b, xpB, EP_);

    // 3. layer-0 recurrence (writes [out_f || out_b] as fp16)
    lstm_layer_kernel<<<NCTA_REC, 256, LSTM_SMEM>>>(xpF, xpB, whF, whB, lens,
                                                    out0, hF, hB);

    // 4. convert layer-1 weights, then input projections (Ka = 2048)
    conv_f16_v4<<<(G4_ * 2048 / 4 + 255) / 256, 256>>>((const float4*)w_ih_l1f, (__half2*)wA, G4_ * 2048 / 4);
    conv_f16_v4<<<(G4_ * 2048 / 4 + 255) / 256, 256>>>((const float4*)w_ih_l1b, (__half2*)wB, G4_ * 2048 / 4);
    conv_f16_v4<<<(G4_ * H_ / 4 + 255) / 256, 256>>>((const float4*)w_hh_l1f, (__half2*)whF, G4_ * H_ / 4);
    conv_f16_v4<<<(G4_ * H_ / 4 + 255) / 256, 256>>>((const float4*)w_hh_l1b, (__half2*)whB, G4_ * H_ / 4);
    gemm_f16<<<gg, 256, GEMM_SMEM>>>(out0, wA, b_ih_l1f, b_hh_l1f, xpF, 2 * H_);
    gemm_f16<<<gg, 256, GEMM_SMEM>>>(out0, wB, b_ih_l1b, b_hh_l1b, xpB, 2 * H_);

    // 5. layer-1 recurrence (only final hiddens needed)
    lstm_layer_kernel<<<NCTA_REC, 256, LSTM_SMEM>>>(xpF, xpB, whF, whB, lens,
                                                    (__half*)nullptr, hF, hB);

    // 6. head
    final_linear_kernel<<<8, 256>>>(hF, hB, lin_w, lin_b, (float*)d_out);
}

// round 8
// speedup vs baseline: 2.9126x; 1.0041x over previous
#include <cuda_runtime.h>
#include <cuda_fp16.h>
#include <cstdint>
#include <cstddef>

// Problem constants
#define B_   32
#define T_   512
#define E_   300
#define EP_  320              // padded embedding K (mult of 32)
#define H_   1024
#define G4_  4096             // 4*H
#define M_   (B_*T_)          // 16384 token rows
#define NCTA_REC 128

// ---------------- scratch (device globals; no allocation allowed) ----------
__device__ __half   g_x   [(size_t)M_ * EP_];      // embedded inputs (fp16)
__device__ __half   g_wA  [(size_t)G4_ * 2048];    // converted w_ih (dir f)
__device__ __half   g_wB  [(size_t)G4_ * 2048];    // converted w_ih (dir b)
__device__ __half   g_whF [(size_t)G4_ * H_];      // converted w_hh fwd (fp16)
__device__ __half   g_whB [(size_t)G4_ * H_];      // converted w_hh bwd (fp16)
__device__ float    g_xpF [(size_t)M_ * G4_];      // input projection fwd
__device__ float    g_xpB [(size_t)M_ * G4_];      // input projection bwd
__device__ __half   g_out0[(size_t)M_ * 2 * H_];   // layer0 output (fp16)
__device__ __half   g_hF  [B_ * H_];               // sorted-row layout
__device__ __half   g_hB  [B_ * H_];
__device__ int      g_idx [M_];                    // compacted row -> b*T+t
__device__ int      g_Mc;                          // number of active rows
__device__ int      g_perm[B_];                    // sorted row -> orig batch
__device__ int      g_nbt [T_];                    // active batches at step t
__device__ int      g_Tmax;                        // max length
__device__ unsigned g_cnt [8 * 32];                // striped counters (4/dir)
__device__ unsigned g_cntm[2 * 32];                // master counter per dir
__device__ volatile unsigned g_bgen[2 * 32];       // barrier gen per dir

// ---------------- helpers ---------------------------------------------------
__device__ __forceinline__ void mma16(float* c, const uint32_t* a, const uint32_t* b) {
    asm volatile(
        "mma.sync.aligned.m16n8k16.row.col.f32.f16.f16.f32 "
        "{%0,%1,%2,%3},{%4,%5,%6,%7},{%8,%9},{%0,%1,%2,%3};"
        : "+f"(c[0]), "+f"(c[1]), "+f"(c[2]), "+f"(c[3])
        : "r"(a[0]), "r"(a[1]), "r"(a[2]), "r"(a[3]), "r"(b[0]), "r"(b[1]));
}

__device__ __forceinline__ void ldsm4(uint32_t* r, uint32_t addr) {
    asm volatile("ldmatrix.sync.aligned.m8n8.x4.shared.b16 {%0,%1,%2,%3}, [%4];"
        : "=r"(r[0]), "=r"(r[1]), "=r"(r[2]), "=r"(r[3]) : "r"(addr));
}

__device__ __forceinline__ float sigmoidf_(float x) { return 1.f / (1.f + __expf(-x)); }

__device__ __forceinline__ uint32_t s2u(const void* p) {
    uint32_t r;
    asm("{ .reg .u64 t; cvta.to.shared.u64 t, %1; cvt.u32.u64 %0, t; }" : "=r"(r) : "l"(p));
    return r;
}
__device__ __forceinline__ void cp16(void* smem, const void* gmem) {
    asm volatile("cp.async.cg.shared.global [%0], [%1], 16;\n" :: "r"(s2u(smem)), "l"(gmem));
}
__device__ __forceinline__ void cp_commit() { asm volatile("cp.async.commit_group;"); }
template<int N> __device__ __forceinline__ void cp_wait() {
    asm volatile("cp.async.wait_group %0;" :: "n"(N));
}

// Per-direction grid barrier: 64 CTAs per direction, 4 stripes of 16.
// Monotonic epochs: no resets, safe across kernel instances & graph replays.
__device__ __forceinline__ void grid_barrier(int dir, unsigned epoch) {
    __threadfence();
    __syncthreads();
    if (threadIdx.x == 0) {
        unsigned s = (dir * 4 + (blockIdx.x & 3)) * 32;   // 128B-separated stripes
        unsigned v = atomicAdd(&g_cnt[s], 1u) + 1u;
        if (v == 16u * epoch) {                           // last arrival in stripe
            unsigned a = atomicAdd(&g_cntm[dir * 32], 1u) + 1u;
            if (a == 4u * epoch) {                        // last stripe of this dir
                __threadfence();
                g_bgen[dir * 32] = epoch;
            }
        }
        while (g_bgen[dir * 32] < epoch) { }
    }
    __syncthreads();
}

// ---------------- kernel 0: compacted index + sort + nbt -------------------
__global__ __launch_bounds__(256) void build_idx_kernel(const int* __restrict__ lens)
{
    __shared__ int sl[B_];
    __shared__ int offs[B_];
    int tid = threadIdx.x;
    if (tid < B_) sl[tid] = lens[tid];
    __syncthreads();
    if (tid == 0) {
        int s = 0;
        for (int b = 0; b < B_; b++) { offs[b] = s; s += sl[b]; }
        g_Mc = s;
        // deterministic selection sort, descending length
        int pr[B_];
        for (int i = 0; i < B_; i++) pr[i] = i;
        for (int i = 0; i < B_; i++) {
            int best = i;
            for (int j = i + 1; j < B_; j++)
                if (sl[pr[j]] > sl[pr[best]]) best = j;
            int tmp = pr[i]; pr[i] = pr[best]; pr[best] = tmp;
        }
        int mx = 0;
        for (int i = 0; i < B_; i++) {
            g_perm[i] = pr[i];
            if (sl[i] > mx) mx = sl[i];
        }
        g_Tmax = mx;
    }
    __syncthreads();
    for (int t = tid; t < T_; t += 256) {
        int c = 0;
        for (int b = 0; b < B_; b++) c += (sl[b] > t);
        g_nbt[t] = c;
    }
    for (int b = 0; b < B_; b++) {
        int len = sl[b], o = offs[b];
        for (int t = tid; t < len; t += 256)
            g_idx[o + t] = b * T_ + t;
    }
}

// ---------------- kernel 1: embedding gather (emit fp16, pad to 320) -------
__global__ __launch_bounds__(256) void gather_kernel(
    const int* __restrict__ tok, const float* __restrict__ emb, __half* __restrict__ x)
{
    int i = blockIdx.x * 256 + threadIdx.x;
    if (i >= M_ * EP_) return;
    int bt = i / EP_;
    int e  = i - bt * EP_;
    x[i] = (e < E_) ? __float2half_rn(emb[(size_t)tok[bt] * E_ + e]) : __float2half(0.f);
}

// ---------------- kernel 1b: fp32 -> fp16 convert (with K padding) ---------
__global__ __launch_bounds__(256) void conv_f16_pad(
    const float* __restrict__ src, __half* __restrict__ dst, int N, int K, int Kp)
{
    int i = blockIdx.x * 256 + threadIdx.x;
    if (i >= N * Kp) return;
    int n = i / Kp, k = i - n * Kp;
    dst[i] = (k < K) ? __float2half_rn(src[(size_t)n * K + k]) : __half(0.f);
}

// vectorized fp16 convert (elem count multiple of 4)
__global__ __launch_bounds__(256) void conv_f16_v4(
    const float4* __restrict__ src, __half2* __restrict__ dst, int n4)
{
    int i = blockIdx.x * 256 + threadIdx.x;
    if (i >= n4) return;
    float4 v = src[i];
    dst[2 * i]     = __floats2half2_rn(v.x, v.y);
    dst[2 * i + 1] = __floats2half2_rn(v.z, v.w);
}

// ---------------- kernel 2: fp16 GEMM over compacted rows ------------------
#define GST 3
#define ASTR 40
#define GEMM_SMEM (2 * GST * 128 * ASTR * 2)
__global__ __launch_bounds__(256, 2) void gemm_f16(
    const __half* __restrict__ A, const __half* __restrict__ Bw,
    const float* __restrict__ bias1, const float* __restrict__ bias2,
    float* __restrict__ C, int Ka)
{
    extern __shared__ char smraw[];
    __half* As = (__half*)smraw;                  // GST * 128 * ASTR
    __half* Bs = As + GST * 128 * ASTR;

    const int tid = threadIdx.x, warp = tid >> 5, lane = tid & 31;
    const int m0 = blockIdx.y * 128, n0 = blockIdx.x * 128;
    const int Mc = g_Mc;
    if (m0 >= Mc) return;
    const int wm = (warp >> 1) * 32, wn = (warp & 1) * 64;
    const __half* Bg = Bw + (size_t)n0 * Ka;

    const __half* Arow[2];
#pragma unroll
    for (int i = 0; i < 2; i++) {
        int glob = m0 + (tid >> 2) + 64 * i;
        int src  = g_idx[glob < Mc ? glob : Mc - 1];
        Arow[i] = A + (size_t)src * Ka + (tid & 3) * 8;
    }

    float acc[2][8][4];
#pragma unroll
    for (int i = 0; i < 2; i++)
#pragma unroll
        for (int j = 0; j < 8; j++)
#pragma unroll
            for (int k = 0; k < 4; k++) acc[i][j][k] = 0.f;

    auto issue = [&](int st, int kc) {
#pragma unroll
        for (int i = 0; i < 2; i++) {
            int row = (tid >> 2) + 64 * i, c8 = (tid & 3) * 8;
            cp16(As + st * 128 * ASTR + row * ASTR + c8, Arow[i] + kc);
            cp16(Bs + st * 128 * ASTR + row * ASTR + c8, Bg + (size_t)row * Ka + kc + c8);
        }
    };

    const int nc = Ka >> 5;
    issue(0, 0);  cp_commit();
    issue(1, 32); cp_commit();

    const uint32_t Au = s2u(As), Bu = s2u(Bs);
    const int rpA = (lane & 7) + ((lane >> 3) & 1) * 8;
    const int kpA = (lane >> 4) * 8;
    const int rpB = (lane & 7) + (lane >> 4) * 8;
    const int kpB = ((lane >> 3) & 1) * 8;

    for (int c = 0; c < nc; c++) {
        if (c + 1 < nc) cp_wait<1>(); else cp_wait<0>();
        __syncthreads();
        if (c + 2 < nc) { issue((c + 2) % GST, (c + 2) * 32); cp_commit(); }

        const uint32_t ab = Au + (c % GST) * 128 * ASTR * 2;
        const uint32_t bb = Bu + (c % GST) * 128 * ASTR * 2;
#pragma unroll
        for (int kk = 0; kk < 32; kk += 16) {
            uint32_t af[2][4], bf[4][4];
#pragma unroll
            for (int mt = 0; mt < 2; mt++)
                ldsm4(af[mt], ab + ((wm + mt * 16 + rpA) * ASTR + kpA + kk) * 2);
#pragma unroll
            for (int nt4 = 0; nt4 < 4; nt4++)
                ldsm4(bf[nt4], bb + ((wn + nt4 * 16 + rpB) * ASTR + kpB + kk) * 2);
#pragma unroll
            for (int mt = 0; mt < 2; mt++)
#pragma unroll
                for (int nt4 = 0; nt4 < 4; nt4++) {
                    mma16(acc[mt][nt4 * 2],     af[mt], bf[nt4]);
                    mma16(acc[mt][nt4 * 2 + 1], af[mt], bf[nt4] + 2);
                }
        }
    }

    int rg[4]; size_t drow[4]; bool val[4];
#pragma unroll
    for (int mt = 0; mt < 2; mt++) {
        rg[mt * 2]     = m0 + wm + mt * 16 + (lane >> 2);
        rg[mt * 2 + 1] = rg[mt * 2] + 8;
    }
#pragma unroll
    for (int i = 0; i < 4; i++) {
        val[i]  = rg[i] < Mc;
        drow[i] = val[i] ? (size_t)g_idx[rg[i]] * G4_ : 0;
    }
#pragma unroll
    for (int mt = 0; mt < 2; mt++)
#pragma unroll
        for (int nt = 0; nt < 8; nt++) {
            int col = n0 + wn + nt * 8 + 2 * (lane & 3);
            float bv0 = bias1[col] + bias2[col];
            float bv1 = bias1[col + 1] + bias2[col + 1];
            if (val[mt * 2]) {
                C[drow[mt * 2] + col]     = acc[mt][nt][0] + bv0;
                C[drow[mt * 2] + col + 1] = acc[mt][nt][1] + bv1;
            }
            if (val[mt * 2 + 1]) {
                C[drow[mt * 2 + 1] + col]     = acc[mt][nt][2] + bv0;
                C[drow[mt * 2 + 1] + col + 1] = acc[mt][nt][3] + bv1;
            }
        }
}

// ---------------- kernel 3: persistent bi-LSTM layer (fp16, resident W) ----
// Sorted batches, per-direction barriers, pipelined xp prefetch, deferred
// out writes. At step t only nb = g_nbt[t] rows are live.
#define HSTRH 1032            // half-stride, mod 64 == 8 -> conflict-free ldsm
#define LSTM_SMEM ((64 + 32) * HSTRH * 2 + 2*32*64*4 + 512*4 + 512*4 + T_*4 + 64*4 + 128)
__global__ __launch_bounds__(256) void lstm_layer_kernel(
    const float* __restrict__ xpF, const float* __restrict__ xpB,
    const __half* __restrict__ WhF, const __half* __restrict__ WhB,
    const int* __restrict__ lengths,
    __half* __restrict__ out,             // (B*T) x 2H fp16, or nullptr
    __half* __restrict__ hF, __half* __restrict__ hB)
{
    extern __shared__ char smraw[];
    __half* WH  = (__half*)smraw;                 // [64][HSTRH] resident W
    __half* HT  = WH + 64 * HSTRH;                // [32][HSTRH] h tile
    float*  GS0 = (float*)(HT + 32 * HSTRH);      // [32][64] gates, k-half 0
    float*  GS1 = GS0 + 32 * 64;                  // [32][64] gates, k-half 1
    float*  CST = GS1 + 32 * 64;                  // [512]
    float*  HST = CST + 512;                      // [512]
    int*    NBT = (int*)(HST + 512);              // [T_]
    int*    SLEN = NBT + T_;                      // [32] sorted lengths
    int*    SPRM = SLEN + 32;                     // [32] sorted -> orig batch

    const int tid = threadIdx.x, warp = tid >> 5, lane = tid & 31;
    const int cta = blockIdx.x;
    const int dir = cta >> 6;
    const int j0  = (cta & 63) * 16;
    const float*  xp   = dir ? xpB : xpF;
    const __half* Wh   = dir ? WhB : WhF;
    __half*       hdir = dir ? hB : hF;

    unsigned epoch = g_bgen[dir * 32];            // monotonic base

    // init state + sorted lengths/perm + nbt table
    for (int p = tid; p < 512; p += 256) {
        int b = p >> 4, jl = p & 15;
        CST[p] = 0.f; HST[p] = 0.f;
        hdir[b * H_ + j0 + jl] = __float2half(0.f);
    }
    if (tid < 32) {
        int pb = g_perm[tid];
        SPRM[tid] = pb;
        SLEN[tid] = lengths[pb];
    }
    for (int i = tid; i < T_; i += 256) NBT[i] = g_nbt[i];
    const int Tmax = g_Tmax;
    // load resident W: 64 rows x 1024 halves = 8192 cp16
#pragma unroll
    for (int i = 0; i < 32; i++) {
        int seg = tid + i * 256;
        int r = seg >> 7, c8 = (seg & 127) * 8;
        cp16(WH + r * HSTRH + c8,
             Wh + ((size_t)((r >> 4) * H_ + j0 + (r & 15))) * H_ + c8);
    }
    cp_commit(); cp_wait<0>();
    grid_barrier(dir, ++epoch);

    const uint32_t HTu = s2u(HT);
    const uint32_t WHu = s2u(WH);
    const int kh  = warp >> 2;                    // k-half (0/1)
    const int wq  = warp & 3;                     // n-quarter
    const int kb  = kh * 512;                     // k base (halves)
    const int rpA = (lane & 7) + ((lane >> 3) & 1) * 8;
    const int kpA = (lane >> 4) * 8;
    const uint32_t aB0 = HTu + ((0  + rpA) * HSTRH + kpA + kb) * 2;
    const uint32_t aB1 = HTu + ((16 + rpA) * HSTRH + kpA + kb) * 2;
    const int rpB = wq * 16 + (lane & 7) + (lane >> 4) * 8;
    const int kpB = ((lane >> 3) & 1) * 8;
    const uint32_t bB0 = WHu + (rpB * HSTRH + kpB + kb) * 2;
    float* GSw = kh ? GS1 : GS0;

    auto issueHC = [&](int colbase, int nrow8) {
        for (int i = 0; i < nrow8; i++) {
            int seg = tid + i * 256;
            int row = seg >> 5, c8 = (seg & 31) * 8;
            cp16(HT + row * HSTRH + colbase + c8, hdir + row * H_ + colbase + c8);
        }
    };

    auto prefetchXP = [&](int t, float xr[2][4], bool act[2]) {
#pragma unroll
        for (int p2 = 0; p2 < 2; p2++) {
            int p = tid + p2 * 256, b = p >> 4, jl = p & 15;
            act[p2] = (t < SLEN[b]);
            if (act[p2]) {
                int pb = SPRM[b];
                int teff = dir ? (SLEN[b] - 1 - t) : t;
                const float* xb = xp + ((size_t)(pb * T_ + teff)) * G4_ + j0 + jl;
                xr[p2][0] = __ldcs(xb);
                xr[p2][1] = __ldcs(xb + H_);
                xr[p2][2] = __ldcs(xb + 2 * H_);
                xr[p2][3] = __ldcs(xb + 3 * H_);
            }
        }
    };

    float xr[2][4];  bool act[2];
    float xrn[2][4]; bool actn[2];
    prefetchXP(0, xr, act);

    __half outh[2];                     // deferred out values (layer 0)
    int    outix[2];
    bool   outa[2] = { false, false };

    for (int t = 0; t < Tmax; t++) {
        const int nb = NBT[t];
        const bool full = nb > 16;
        const int nrow8 = full ? 4 : 2;

        // issue h chunks: phase-1 chunks of both k-halves first
        issueHC(0,   nrow8); cp_commit();
        issueHC(512, nrow8); cp_commit();
        issueHC(256, nrow8); cp_commit();
        issueHC(768, nrow8); cp_commit();

        // deferred out writes from step t-1 (overlap h load)
        if (out) {
#pragma unroll
            for (int p2 = 0; p2 < 2; p2++)
                if (outa[p2]) out[outix[p2]] = outh[p2];
        }
        // prefetch next step's xp (overlaps MMA below)
        if (t + 1 < Tmax) prefetchXP(t + 1, xrn, actn);

        float acc[2][2][4];
#pragma unroll
        for (int a = 0; a < 2; a++)
#pragma unroll
            for (int b = 0; b < 2; b++)
#pragma unroll
                for (int k = 0; k < 4; k++) acc[a][b][k] = 0.f;

        // phase 1
        cp_wait<2>();
        __syncthreads();
#pragma unroll 4
        for (int k = 0; k < 256; k += 16) {
            uint32_t a0[4], bb[4];
            ldsm4(a0, aB0 + k * 2);
            ldsm4(bb, bB0 + k * 2);
            mma16(acc[0][0], a0, bb);
            mma16(acc[0][1], a0, bb + 2);
            if (full) {
                uint32_t a1[4];
                ldsm4(a1, aB1 + k * 2);
                mma16(acc[1][0], a1, bb);
                mma16(acc[1][1], a1, bb + 2);
            }
        }

        // phase 2
        cp_wait<0>();
        __syncthreads();
#pragma unroll 4
        for (int k = 256; k < 512; k += 16) {
            uint32_t a0[4], bb[4];
            ldsm4(a0, aB0 + k * 2);
            ldsm4(bb, bB0 + k * 2);
            mma16(acc[0][0], a0, bb);
            mma16(acc[0][1], a0, bb + 2);
            if (full) {
                uint32_t a1[4];
                ldsm4(a1, aB1 + k * 2);
                mma16(acc[1][0], a1, bb);
                mma16(acc[1][1], a1, bb + 2);
            }
        }

        // dump gate fragments
        {
            int rowb = lane >> 2, colb = wq * 16 + 2 * (lane & 3);
#pragma unroll
            for (int nt = 0; nt < 2; nt++) {
                GSw[rowb * 64 + colb + nt * 8]           = acc[0][nt][0];
                GSw[rowb * 64 + colb + nt * 8 + 1]       = acc[0][nt][1];
                GSw[(rowb + 8) * 64 + colb + nt * 8]     = acc[0][nt][2];
                GSw[(rowb + 8) * 64 + colb + nt * 8 + 1] = acc[0][nt][3];
            }
            if (full) {
#pragma unroll
                for (int nt = 0; nt < 2; nt++) {
                    GSw[(16 + rowb) * 64 + colb + nt * 8]     = acc[1][nt][0];
                    GSw[(16 + rowb) * 64 + colb + nt * 8 + 1] = acc[1][nt][1];
                    GSw[(24 + rowb) * 64 + colb + nt * 8]     = acc[1][nt][2];
                    GSw[(24 + rowb) * 64 + colb + nt * 8 + 1] = acc[1][nt][3];
                }
            }
        }
        __syncthreads();

        // LSTM cell (live rows only); out writes deferred past the barrier
#pragma unroll
        for (int p2 = 0; p2 < 2; p2++) {
            if (!act[p2]) { outa[p2] = false; continue; }
            int p = tid + p2 * 256, b = p >> 4, jl = p & 15;
            float gi = GS0[b * 64 + jl]      + GS1[b * 64 + jl]      + xr[p2][0];
            float gf = GS0[b * 64 + 16 + jl] + GS1[b * 64 + 16 + jl] + xr[p2][1];
            float gg = GS0[b * 64 + 32 + jl] + GS1[b * 64 + 32 + jl] + xr[p2][2];
            float go = GS0[b * 64 + 48 + jl] + GS1[b * 64 + 48 + jl] + xr[p2][3];
            float ii = sigmoidf_(gi), ff = sigmoidf_(gf);
            float gv = tanhf(gg),     oo = sigmoidf_(go);
            float cn = ff * CST[p] + ii * gv;
            float hn = oo * tanhf(cn);
            CST[p] = cn; HST[p] = hn;
            __half hh = __float2half_rn(hn);
            hdir[b * H_ + j0 + jl] = hh;
            if (out) {
                int pb = SPRM[b];
                int pout = dir ? (SLEN[b] - 1 - t) : t;
                outh[p2] = hh;
                outix[p2] = (pb * T_ + pout) * (2 * H_) + dir * H_ + j0 + jl;
                outa[p2] = true;
            }
        }
        grid_barrier(dir, ++epoch);

        // rotate prefetched xp
#pragma unroll
        for (int p2 = 0; p2 < 2; p2++) {
            act[p2] = actn[p2];
#pragma unroll
            for (int q = 0; q < 4; q++) xr[p2][q] = xrn[p2][q];
        }
    }
    // flush last step's deferred out writes
    if (out) {
#pragma unroll
        for (int p2 = 0; p2 < 2; p2++)
            if (outa[p2]) out[outix[p2]] = outh[p2];
    }
}

// ---------------- kernel 4: final linear  out = [h2b, h2f] @ lin_w^T + b ---
__global__ __launch_bounds__(256) void final_linear_kernel(
    const __half* __restrict__ hF, const __half* __restrict__ hB,
    const float* __restrict__ lw, const float* __restrict__ lb,
    float* __restrict__ outp)
{
    int w = (blockIdx.x * blockDim.x + threadIdx.x) >> 5;
    int lane = threadIdx.x & 31;
    if (w >= B_ * 2) return;
    int b = w >> 1, c = w & 1;          // b = sorted row
    int pb = g_perm[b];                  // original batch
    float s = 0.f;
    for (int k = lane; k < 2 * H_; k += 32) {
        float xv = __half2float((k < H_) ? hB[b * H_ + k] : hF[b * H_ + (k - H_)]);
        s += xv * lw[c * 2 * H_ + k];
    }
#pragma unroll
    for (int o = 16; o; o >>= 1) s += __shfl_xor_sync(0xffffffffu, s, o);
    if (lane == 0) outp[pb * 2 + c] = s + lb[c];
}

// ---------------- launch ----------------------------------------------------
extern "C" void kernel_launch(void* const* d_in, const int* in_sizes, int n_in,
                              void* d_out, int out_size)
{
    const int*   tok      = (const int*)  d_in[0];
    const int*   lens     = (const int*)  d_in[1];
    const float* emb      = (const float*)d_in[2];
    const float* w_ih_l0f = (const float*)d_in[3];
    const float* w_hh_l0f = (const float*)d_in[4];
    const float* b_ih_l0f = (const float*)d_in[5];
    const float* b_hh_l0f = (const float*)d_in[6];
    const float* w_ih_l0b = (const float*)d_in[7];
    const float* w_hh_l0b = (const float*)d_in[8];
    const float* b_ih_l0b = (const float*)d_in[9];
    const float* b_hh_l0b = (const float*)d_in[10];
    const float* w_ih_l1f = (const float*)d_in[11];
    const float* w_hh_l1f = (const float*)d_in[12];
    const float* b_ih_l1f = (const float*)d_in[13];
    const float* b_hh_l1f = (const float*)d_in[14];
    const float* w_ih_l1b = (const float*)d_in[15];
    const float* w_hh_l1b = (const float*)d_in[16];
    const float* b_ih_l1b = (const float*)d_in[17];
    const float* b_hh_l1b = (const float*)d_in[18];
    const float* lin_w    = (const float*)d_in[19];
    const float* lin_b    = (const float*)d_in[20];

    __half *x, *wA, *wB, *whF, *whB, *out0, *hF, *hB;
    float *xpF, *xpB;
    cudaGetSymbolAddress((void**)&x,    g_x);
    cudaGetSymbolAddress((void**)&wA,   g_wA);
    cudaGetSymbolAddress((void**)&wB,   g_wB);
    cudaGetSymbolAddress((void**)&whF,  g_whF);
    cudaGetSymbolAddress((void**)&whB,  g_whB);
    cudaGetSymbolAddress((void**)&xpF,  g_xpF);
    cudaGetSymbolAddress((void**)&xpB,  g_xpB);
    cudaGetSymbolAddress((void**)&out0, g_out0);
    cudaGetSymbolAddress((void**)&hF,   g_hF);
    cudaGetSymbolAddress((void**)&hB,   g_hB);

    cudaFuncSetAttribute(gemm_f16, cudaFuncAttributeMaxDynamicSharedMemorySize, GEMM_SMEM);
    cudaFuncSetAttribute(lstm_layer_kernel, cudaFuncAttributeMaxDynamicSharedMemorySize, LSTM_SMEM);

    dim3 gg(G4_ / 128, M_ / 128);

    // 0. compacted row index + sorted perm + nbt
    build_idx_kernel<<<1, 256>>>(lens);

    // 1. embedding gather -> fp16, K padded to 320
    gather_kernel<<<(M_ * EP_ + 255) / 256, 256>>>(tok, emb, x);

    // 2. convert layer-0 weights, then input projections (Ka = 320)
    conv_f16_pad<<<(G4_ * EP_ + 255) / 256, 256>>>(w_ih_l0f, wA, G4_, E_, EP_);
    conv_f16_pad<<<(G4_ * EP_ + 255) / 256, 256>>>(w_ih_l0b, wB, G4_, E_, EP_);
    conv_f16_v4<<<(G4_ * H_ / 4 + 255) / 256, 256>>>((const float4*)w_hh_l0f, (__half2*)whF, G4_ * H_ / 4);
    conv_f16_v4<<<(G4_ * H_ / 4 + 255) / 256, 256>>>((const float4*)w_hh_l0b, (__half2*)whB, G4_ * H_ / 4);
    gemm_f16<<<gg, 256, GEMM_SMEM>>>(x, wA, b_ih_l0f, b_hh_l0f, xpF, EP_);
    gemm_f16<<<gg, 256, GEMM_SMEM>>>(x, wB, b_ih_l0b, b_hh_l0b, xpB, EP_);

    // 3. layer-0 recurrence (writes [out_f || out_b] as fp16)
    lstm_layer_kernel<<<NCTA_REC, 256, LSTM_SMEM>>>(xpF, xpB, whF, whB, lens,
                                                    out0, hF, hB);

    // 4. convert layer-1 weights, then input projections (Ka = 2048)
    conv_f16_v4<<<(G4_ * 2048 / 4 + 255) / 256, 256>>>((const float4*)w_ih_l1f, (__half2*)wA, G4_ * 2048 / 4);
    conv_f16_v4<<<(G4_ * 2048 / 4 + 255) / 256, 256>>>((const float4*)w_ih_l1b, (__half2*)wB, G4_ * 2048 / 4);
    conv_f16_v4<<<(G4_ * H_ / 4 + 255) / 256, 256>>>((const float4*)w_hh_l1f, (__half2*)whF, G4_ * H_ / 4);
    conv_f16_v4<<<(G4_ * H_ / 4 + 255) / 256, 256>>>((const float4*)w_hh_l1b, (__half2*)whB, G4_ * H_ / 4);
    gemm_f16<<<gg, 256, GEMM_SMEM>>>(out0, wA, b_ih_l1f, b_hh_l1f, xpF, 2 * H_);
    gemm_f16<<<gg, 256, GEMM_SMEM>>>(out0, wB, b_ih_l1b, b_hh_l1b, xpB, 2 * H_);

    // 5. layer-1 recurrence (only final hiddens needed)
    lstm_layer_kernel<<<NCTA_REC, 256, LSTM_SMEM>>>(xpF, xpB, whF, whB, lens,
                                                    (__half*)nullptr, hF, hB);

    // 6. head
    final_linear_kernel<<<8, 256>>>(hF, hB, lin_w, lin_b, (float*)d_out);
}

// round 10
// speedup vs baseline: 2.9504x; 1.0130x over previous
#include <cuda_runtime.h>
#include <cuda_fp16.h>
#include <cstdint>
#include <cstddef>

// Problem constants
#define B_   32
#define T_   512
#define E_   300
#define EP_  320              // padded embedding K (mult of 32)
#define H_   1024
#define G4_  4096             // 4*H
#define M_   (B_*T_)          // 16384 token rows
#define NCTA_REC 128

// ---------------- scratch (device globals; no allocation allowed) ----------
__device__ __half   g_x   [(size_t)M_ * EP_];      // embedded inputs (fp16)
__device__ __half   g_wA  [(size_t)G4_ * 2048];    // converted w_ih (dir f)
__device__ __half   g_wB  [(size_t)G4_ * 2048];    // converted w_ih (dir b)
__device__ __half   g_whF [(size_t)G4_ * H_];      // converted w_hh fwd (fp16)
__device__ __half   g_whB [(size_t)G4_ * H_];      // converted w_hh bwd (fp16)
__device__ float    g_xpF [(size_t)M_ * G4_];      // input projection fwd
__device__ float    g_xpB [(size_t)M_ * G4_];      // input projection bwd
__device__ __half   g_out0[(size_t)M_ * 2 * H_];   // layer0 output (fp16)
__device__ __half   g_hF  [B_ * H_];               // sorted-row layout
__device__ __half   g_hB  [B_ * H_];
__device__ int      g_idx [M_];                    // compacted row -> b*T+t
__device__ int      g_Mc;                          // number of active rows
__device__ int      g_perm[B_];                    // sorted row -> orig batch
__device__ int      g_nbt [T_];                    // active batches at step t
__device__ int      g_Tmax;                        // max length
__device__ unsigned g_cnt [8 * 32];                // striped counters (4/dir)
__device__ unsigned g_cntm[2 * 32];                // master counter per dir
__device__ volatile unsigned g_bgen[2 * 32];       // barrier gen per dir

// ---------------- helpers ---------------------------------------------------
__device__ __forceinline__ void mma16(float* c, const uint32_t* a, const uint32_t* b) {
    asm volatile(
        "mma.sync.aligned.m16n8k16.row.col.f32.f16.f16.f32 "
        "{%0,%1,%2,%3},{%4,%5,%6,%7},{%8,%9},{%0,%1,%2,%3};"
        : "+f"(c[0]), "+f"(c[1]), "+f"(c[2]), "+f"(c[3])
        : "r"(a[0]), "r"(a[1]), "r"(a[2]), "r"(a[3]), "r"(b[0]), "r"(b[1]));
}

__device__ __forceinline__ void ldsm4(uint32_t* r, uint32_t addr) {
    asm volatile("ldmatrix.sync.aligned.m8n8.x4.shared.b16 {%0,%1,%2,%3}, [%4];"
        : "=r"(r[0]), "=r"(r[1]), "=r"(r[2]), "=r"(r[3]) : "r"(addr));
}

__device__ __forceinline__ float sigmoidf_(float x) { return 1.f / (1.f + __expf(-x)); }

__device__ __forceinline__ uint32_t s2u(const void* p) {
    uint32_t r;
    asm("{ .reg .u64 t; cvta.to.shared.u64 t, %1; cvt.u32.u64 %0, t; }" : "=r"(r) : "l"(p));
    return r;
}
__device__ __forceinline__ void cp16(void* smem, const void* gmem) {
    asm volatile("cp.async.cg.shared.global [%0], [%1], 16;\n" :: "r"(s2u(smem)), "l"(gmem));
}
__device__ __forceinline__ void cp_commit() { asm volatile("cp.async.commit_group;"); }
template<int N> __device__ __forceinline__ void cp_wait() {
    asm volatile("cp.async.wait_group %0;" :: "n"(N));
}

// Per-direction grid barrier: 64 CTAs per direction, 4 stripes of 16.
// Monotonic epochs: no resets, safe across kernel instances & graph replays.
__device__ __forceinline__ void grid_barrier(int dir, unsigned epoch) {
    __threadfence();
    __syncthreads();
    if (threadIdx.x == 0) {
        unsigned s = (dir * 4 + (blockIdx.x & 3)) * 32;
        unsigned v = atomicAdd(&g_cnt[s], 1u) + 1u;
        if (v == 16u * epoch) {
            unsigned a = atomicAdd(&g_cntm[dir * 32], 1u) + 1u;
            if (a == 4u * epoch) {
                __threadfence();
                g_bgen[dir * 32] = epoch;
            }
        }
        while (g_bgen[dir * 32] < epoch) { }
    }
    __syncthreads();
}

// ---------------- kernel 0: compacted index + sort + nbt -------------------
__global__ __launch_bounds__(256) void build_idx_kernel(const int* __restrict__ lens)
{
    __shared__ int sl[B_];
    __shared__ int offs[B_];
    int tid = threadIdx.x;
    if (tid < B_) sl[tid] = lens[tid];
    __syncthreads();
    if (tid == 0) {
        int s = 0;
        for (int b = 0; b < B_; b++) { offs[b] = s; s += sl[b]; }
        g_Mc = s;
        int pr[B_];
        for (int i = 0; i < B_; i++) pr[i] = i;
        for (int i = 0; i < B_; i++) {
            int best = i;
            for (int j = i + 1; j < B_; j++)
                if (sl[pr[j]] > sl[pr[best]]) best = j;
            int tmp = pr[i]; pr[i] = pr[best]; pr[best] = tmp;
        }
        int mx = 0;
        for (int i = 0; i < B_; i++) {
            g_perm[i] = pr[i];
            if (sl[i] > mx) mx = sl[i];
        }
        g_Tmax = mx;
    }
    __syncthreads();
    for (int t = tid; t < T_; t += 256) {
        int c = 0;
        for (int b = 0; b < B_; b++) c += (sl[b] > t);
        g_nbt[t] = c;
    }
    for (int b = 0; b < B_; b++) {
        int len = sl[b], o = offs[b];
        for (int t = tid; t < len; t += 256)
            g_idx[o + t] = b * T_ + t;
    }
}

// ---------------- kernel 1: embedding gather (emit fp16, pad to 320) -------
__global__ __launch_bounds__(256) void gather_kernel(
    const int* __restrict__ tok, const float* __restrict__ emb, __half* __restrict__ x)
{
    int i = blockIdx.x * 256 + threadIdx.x;
    if (i >= M_ * EP_) return;
    int bt = i / EP_;
    int e  = i - bt * EP_;
    x[i] = (e < E_) ? __float2half_rn(emb[(size_t)tok[bt] * E_ + e]) : __float2half(0.f);
}

// ---------------- kernel 1b: fp32 -> fp16 convert (with K padding) ---------
__global__ __launch_bounds__(256) void conv_f16_pad(
    const float* __restrict__ src, __half* __restrict__ dst, int N, int K, int Kp)
{
    int i = blockIdx.x * 256 + threadIdx.x;
    if (i >= N * Kp) return;
    int n = i / Kp, k = i - n * Kp;
    dst[i] = (k < K) ? __float2half_rn(src[(size_t)n * K + k]) : __half(0.f);
}

__global__ __launch_bounds__(256) void conv_f16_v4(
    const float4* __restrict__ src, __half2* __restrict__ dst, int n4)
{
    int i = blockIdx.x * 256 + threadIdx.x;
    if (i >= n4) return;
    float4 v = src[i];
    dst[2 * i]     = __floats2half2_rn(v.x, v.y);
    dst[2 * i + 1] = __floats2half2_rn(v.z, v.w);
}

// ---------------- kernel 2: fp16 GEMM over compacted rows ------------------
#define GST 3
#define ASTR 40
#define GEMM_SMEM (2 * GST * 128 * ASTR * 2)
__global__ __launch_bounds__(256, 2) void gemm_f16(
    const __half* __restrict__ A, const __half* __restrict__ Bw,
    const float* __restrict__ bias1, const float* __restrict__ bias2,
    float* __restrict__ C, int Ka)
{
    extern __shared__ char smraw[];
    __half* As = (__half*)smraw;                  // GST * 128 * ASTR
    __half* Bs = As + GST * 128 * ASTR;

    const int tid = threadIdx.x, warp = tid >> 5, lane = tid & 31;
    const int m0 = blockIdx.y * 128, n0 = blockIdx.x * 128;
    const int Mc = g_Mc;
    if (m0 >= Mc) return;
    const int wm = (warp >> 1) * 32, wn = (warp & 1) * 64;
    const __half* Bg = Bw + (size_t)n0 * Ka;

    const __half* Arow[2];
#pragma unroll
    for (int i = 0; i < 2; i++) {
        int glob = m0 + (tid >> 2) + 64 * i;
        int src  = g_idx[glob < Mc ? glob : Mc - 1];
        Arow[i] = A + (size_t)src * Ka + (tid & 3) * 8;
    }

    float acc[2][8][4];
#pragma unroll
    for (int i = 0; i < 2; i++)
#pragma unroll
        for (int j = 0; j < 8; j++)
#pragma unroll
            for (int k = 0; k < 4; k++) acc[i][j][k] = 0.f;

    auto issue = [&](int st, int kc) {
#pragma unroll
        for (int i = 0; i < 2; i++) {
            int row = (tid >> 2) + 64 * i, c8 = (tid & 3) * 8;
            cp16(As + st * 128 * ASTR + row * ASTR + c8, Arow[i] + kc);
            cp16(Bs + st * 128 * ASTR + row * ASTR + c8, Bg + (size_t)row * Ka + kc + c8);
        }
    };

    const int nc = Ka >> 5;
    issue(0, 0);  cp_commit();
    issue(1, 32); cp_commit();

    const uint32_t Au = s2u(As), Bu = s2u(Bs);
    const int rpA = (lane & 7) + ((lane >> 3) & 1) * 8;
    const int kpA = (lane >> 4) * 8;
    const int rpB = (lane & 7) + (lane >> 4) * 8;
    const int kpB = ((lane >> 3) & 1) * 8;

    for (int c = 0; c < nc; c++) {
        if (c + 1 < nc) cp_wait<1>(); else cp_wait<0>();
        __syncthreads();
        if (c + 2 < nc) { issue((c + 2) % GST, (c + 2) * 32); cp_commit(); }

        const uint32_t ab = Au + (c % GST) * 128 * ASTR * 2;
        const uint32_t bb = Bu + (c % GST) * 128 * ASTR * 2;
#pragma unroll
        for (int kk = 0; kk < 32; kk += 16) {
            uint32_t af[2][4], bf[4][4];
#pragma unroll
            for (int mt = 0; mt < 2; mt++)
                ldsm4(af[mt], ab + ((wm + mt * 16 + rpA) * ASTR + kpA + kk) * 2);
#pragma unroll
            for (int nt4 = 0; nt4 < 4; nt4++)
                ldsm4(bf[nt4], bb + ((wn + nt4 * 16 + rpB) * ASTR + kpB + kk) * 2);
#pragma unroll
            for (int mt = 0; mt < 2; mt++)
#pragma unroll
                for (int nt4 = 0; nt4 < 4; nt4++) {
                    mma16(acc[mt][nt4 * 2],     af[mt], bf[nt4]);
                    mma16(acc[mt][nt4 * 2 + 1], af[mt], bf[nt4] + 2);
                }
        }
    }

    int rg[4]; size_t drow[4]; bool val[4];
#pragma unroll
    for (int mt = 0; mt < 2; mt++) {
        rg[mt * 2]     = m0 + wm + mt * 16 + (lane >> 2);
        rg[mt * 2 + 1] = rg[mt * 2] + 8;
    }
#pragma unroll
    for (int i = 0; i < 4; i++) {
        val[i]  = rg[i] < Mc;
        drow[i] = val[i] ? (size_t)g_idx[rg[i]] * G4_ : 0;
    }
#pragma unroll
    for (int mt = 0; mt < 2; mt++)
#pragma unroll
        for (int nt = 0; nt < 8; nt++) {
            int col = n0 + wn + nt * 8 + 2 * (lane & 3);
            float bv0 = bias1[col] + bias2[col];
            float bv1 = bias1[col + 1] + bias2[col + 1];
            if (val[mt * 2]) {
                C[drow[mt * 2] + col]     = acc[mt][nt][0] + bv0;
                C[drow[mt * 2] + col + 1] = acc[mt][nt][1] + bv1;
            }
            if (val[mt * 2 + 1]) {
                C[drow[mt * 2 + 1] + col]     = acc[mt][nt][2] + bv0;
                C[drow[mt * 2 + 1] + col + 1] = acc[mt][nt][3] + bv1;
            }
        }
}

// ---------------- kernel 3: persistent bi-LSTM layer (fp16, resident W) ----
// 8 warps = 4 k-quarters (k=256) x 2 n-halves (n=32): minimizes smem-crossbar
// traffic (262KB/step vs 384KB). Gate partials: 4 buffers ALIASING the h tile
// (dead between MMA end and next step's load). Phase A: quarters 0-1 compute
// on h chunks 0-1 while chunks 2-3 stream; phase B: quarters 2-3.
#define HSTRH 1032            // half-stride, mod 64 == 8 -> conflict-free ldsm
#define LSTM_SMEM ((64 + 32) * HSTRH * 2 + 512*4 + 512*4 + T_*4 + 64*4 + 128)
__global__ __launch_bounds__(256) void lstm_layer_kernel(
    const float* __restrict__ xpF, const float* __restrict__ xpB,
    const __half* __restrict__ WhF, const __half* __restrict__ WhB,
    const int* __restrict__ lengths,
    __half* __restrict__ out,             // (B*T) x 2H fp16, or nullptr
    __half* __restrict__ hF, __half* __restrict__ hB)
{
    extern __shared__ char smraw[];
    __half* WH  = (__half*)smraw;                 // [64][HSTRH] resident W
    __half* HT  = WH + 64 * HSTRH;                // [32][HSTRH] h tile
    float*  GSB = (float*)HT;                     // [4][32][64] gate partials (ALIAS)
    float*  CST = (float*)(HT + 32 * HSTRH);      // [512]
    float*  HST = CST + 512;                      // [512]
    int*    NBT = (int*)(HST + 512);              // [T_]
    int*    SLEN = NBT + T_;                      // [32] sorted lengths
    int*    SPRM = SLEN + 32;                     // [32] sorted -> orig batch

    const int tid = threadIdx.x, warp = tid >> 5, lane = tid & 31;
    const int cta = blockIdx.x;
    const int dir = cta >> 6;
    const int j0  = (cta & 63) * 16;
    const float*  xp   = dir ? xpB : xpF;
    const __half* Wh   = dir ? WhB : WhF;
    __half*       hdir = dir ? hB : hF;

    unsigned epoch = g_bgen[dir * 32];

    for (int p = tid; p < 512; p += 256) {
        int b = p >> 4, jl = p & 15;
        CST[p] = 0.f; HST[p] = 0.f;
        hdir[b * H_ + j0 + jl] = __float2half(0.f);
    }
    if (tid < 32) {
        int pb = g_perm[tid];
        SPRM[tid] = pb;
        SLEN[tid] = lengths[pb];
    }
    for (int i = tid; i < T_; i += 256) NBT[i] = g_nbt[i];
    const int Tmax = g_Tmax;
#pragma unroll
    for (int i = 0; i < 32; i++) {
        int seg = tid + i * 256;
        int r = seg >> 7, c8 = (seg & 127) * 8;
        cp16(WH + r * HSTRH + c8,
             Wh + ((size_t)((r >> 4) * H_ + j0 + (r & 15))) * H_ + c8);
    }
    cp_commit(); cp_wait<0>();
    grid_barrier(dir, ++epoch);

    const uint32_t HTu = s2u(HT);
    const uint32_t WHu = s2u(WH);
    const int kq  = warp >> 1;                    // k-quarter (0..3)
    const int nh  = warp & 1;                     // n-half (0/1)
    const int kb  = kq * 256;                     // k base (halves)
    const int rpA = (lane & 7) + ((lane >> 3) & 1) * 8;
    const int kpA = (lane >> 4) * 8;
    const uint32_t aB0 = HTu + ((0  + rpA) * HSTRH + kpA + kb) * 2;
    const uint32_t aB1 = HTu + ((16 + rpA) * HSTRH + kpA + kb) * 2;
    const int rpB = nh * 32 + (lane & 7) + (lane >> 4) * 8;
    const int kpB = ((lane >> 3) & 1) * 8;
    const uint32_t bB0 = WHu + (rpB * HSTRH + kpB + kb) * 2;
    const uint32_t bB1 = bB0 + 16 * HSTRH * 2;
    float* GSw = GSB + kq * 32 * 64;

    auto issueHC = [&](int colbase, int nrow8) {
        for (int i = 0; i < nrow8; i++) {
            int seg = tid + i * 256;
            int row = seg >> 5, c8 = (seg & 31) * 8;
            cp16(HT + row * HSTRH + colbase + c8, hdir + row * H_ + colbase + c8);
        }
    };

    auto prefetchXP = [&](int t, float xr[2][4], bool act[2]) {
#pragma unroll
        for (int p2 = 0; p2 < 2; p2++) {
            int p = tid + p2 * 256, b = p >> 4, jl = p & 15;
            act[p2] = (t < SLEN[b]);
            if (act[p2]) {
                int pb = SPRM[b];
                int teff = dir ? (SLEN[b] - 1 - t) : t;
                const float* xb = xp + ((size_t)(pb * T_ + teff)) * G4_ + j0 + jl;
                xr[p2][0] = __ldcs(xb);
                xr[p2][1] = __ldcs(xb + H_);
                xr[p2][2] = __ldcs(xb + 2 * H_);
                xr[p2][3] = __ldcs(xb + 3 * H_);
            }
        }
    };

    float xr[2][4];  bool act[2];
    float xrn[2][4]; bool actn[2];
    prefetchXP(0, xr, act);

    __half outh[2];
    int    outix[2];
    bool   outa[2] = { false, false };

    for (int t = 0; t < Tmax; t++) {
        const int nb = NBT[t];
        const bool full = nb > 16;
        const int nrow8 = full ? 4 : 2;

        // issue h chunks in k order (quarter q consumes chunk q)
        issueHC(0,   nrow8); cp_commit();
        issueHC(256, nrow8); cp_commit();
        issueHC(512, nrow8); cp_commit();
        issueHC(768, nrow8); cp_commit();

        // deferred out writes from step t-1 (overlap h load)
        if (out) {
#pragma unroll
            for (int p2 = 0; p2 < 2; p2++)
                if (outa[p2]) out[outix[p2]] = outh[p2];
        }
        // prefetch next step's xp (overlaps MMA below)
        if (t + 1 < Tmax) prefetchXP(t + 1, xrn, actn);

        float acc[2][4][4];
#pragma unroll
        for (int a = 0; a < 2; a++)
#pragma unroll
            for (int b = 0; b < 4; b++)
#pragma unroll
                for (int k = 0; k < 4; k++) acc[a][b][k] = 0.f;

        // phase A: chunks 0,1 resident -> quarters 0,1 compute
        cp_wait<2>();
        __syncthreads();
        if (kq < 2) {
#pragma unroll 4
            for (int k = 0; k < 256; k += 16) {
                uint32_t a0[4], b0[4], b1[4];
                ldsm4(a0, aB0 + k * 2);
                ldsm4(b0, bB0 + k * 2);
                ldsm4(b1, bB1 + k * 2);
                mma16(acc[0][0], a0, b0);
                mma16(acc[0][1], a0, b0 + 2);
                mma16(acc[0][2], a0, b1);
                mma16(acc[0][3], a0, b1 + 2);
                if (full) {
                    uint32_t a1[4];
                    ldsm4(a1, aB1 + k * 2);
                    mma16(acc[1][0], a1, b0);
                    mma16(acc[1][1], a1, b0 + 2);
                    mma16(acc[1][2], a1, b1);
                    mma16(acc[1][3], a1, b1 + 2);
                }
            }
        }

        // phase B: chunks 2,3 resident -> quarters 2,3 compute
        cp_wait<0>();
        __syncthreads();
        if (kq >= 2) {
#pragma unroll 4
            for (int k = 0; k < 256; k += 16) {
                uint32_t a0[4], b0[4], b1[4];
                ldsm4(a0, aB0 + k * 2);
                ldsm4(b0, bB0 + k * 2);
                ldsm4(b1, bB1 + k * 2);
                mma16(acc[0][0], a0, b0);
                mma16(acc[0][1], a0, b0 + 2);
                mma16(acc[0][2], a0, b1);
                mma16(acc[0][3], a0, b1 + 2);
                if (full) {
                    uint32_t a1[4];
                    ldsm4(a1, aB1 + k * 2);
                    mma16(acc[1][0], a1, b0);
                    mma16(acc[1][1], a1, b0 + 2);
                    mma16(acc[1][2], a1, b1);
                    mma16(acc[1][3], a1, b1 + 2);
                }
            }
        }
        __syncthreads();     // all HT ldsm done before GS alias writes

        // dump gate partials: warp owns cols [nh*32, nh*32+32) of GSB[kq]
        {
            int rowb = lane >> 2, colb = nh * 32 + 2 * (lane & 3);
#pragma unroll
            for (int nt = 0; nt < 4; nt++) {
                GSw[rowb * 64 + colb + nt * 8]           = acc[0][nt][0];
                GSw[rowb * 64 + colb + nt * 8 + 1]       = acc[0][nt][1];
                GSw[(rowb + 8) * 64 + colb + nt * 8]     = acc[0][nt][2];
                GSw[(rowb + 8) * 64 + colb + nt * 8 + 1] = acc[0][nt][3];
            }
            if (full) {
#pragma unroll
                for (int nt = 0; nt < 4; nt++) {
                    GSw[(16 + rowb) * 64 + colb + nt * 8]     = acc[1][nt][0];
                    GSw[(16 + rowb) * 64 + colb + nt * 8 + 1] = acc[1][nt][1];
                    GSw[(24 + rowb) * 64 + colb + nt * 8]     = acc[1][nt][2];
                    GSw[(24 + rowb) * 64 + colb + nt * 8 + 1] = acc[1][nt][3];
                }
            }
        }
        __syncthreads();

        // LSTM cell (live rows only); sum the 4 k-quarter partials
#pragma unroll
        for (int p2 = 0; p2 < 2; p2++) {
            if (!act[p2]) { outa[p2] = false; continue; }
            int p = tid + p2 * 256, b = p >> 4, jl = p & 15;
            float gi = xr[p2][0], gf = xr[p2][1], gg = xr[p2][2], go = xr[p2][3];
#pragma unroll
            for (int q = 0; q < 4; q++) {
                const float* G = GSB + q * 32 * 64 + b * 64;
                gi += G[jl];
                gf += G[16 + jl];
                gg += G[32 + jl];
                go += G[48 + jl];
            }
            float ii = sigmoidf_(gi), ff = sigmoidf_(gf);
            float gv = tanhf(gg),     oo = sigmoidf_(go);
            float cn = ff * CST[p] + ii * gv;
            float hn = oo * tanhf(cn);
            CST[p] = cn; HST[p] = hn;
            __half hh = __float2half_rn(hn);
            hdir[b * H_ + j0 + jl] = hh;
            if (out) {
                int pb = SPRM[b];
                int pout = dir ? (SLEN[b] - 1 - t) : t;
                outh[p2] = hh;
                outix[p2] = (pb * T_ + pout) * (2 * H_) + dir * H_ + j0 + jl;
                outa[p2] = true;
            }
        }
        grid_barrier(dir, ++epoch);

#pragma unroll
        for (int p2 = 0; p2 < 2; p2++) {
            act[p2] = actn[p2];
#pragma unroll
            for (int q = 0; q < 4; q++) xr[p2][q] = xrn[p2][q];
        }
    }
    if (out) {
#pragma unroll
        for (int p2 = 0; p2 < 2; p2++)
            if (outa[p2]) out[outix[p2]] = outh[p2];
    }
}

// ---------------- kernel 4: final linear  out = [h2b, h2f] @ lin_w^T + b ---
__global__ __launch_bounds__(256) void final_linear_kernel(
    const __half* __restrict__ hF, const __half* __restrict__ hB,
    const float* __restrict__ lw, const float* __restrict__ lb,
    float* __restrict__ outp)
{
    int w = (blockIdx.x * blockDim.x + threadIdx.x) >> 5;
    int lane = threadIdx.x & 31;
    if (w >= B_ * 2) return;
    int b = w >> 1, c = w & 1;
    int pb = g_perm[b];
    float s = 0.f;
    for (int k = lane; k < 2 * H_; k += 32) {
        float xv = __half2float((k < H_) ? hB[b * H_ + k] : hF[b * H_ + (k - H_)]);
        s += xv * lw[c * 2 * H_ + k];
    }
#pragma unroll
    for (int o = 16; o; o >>= 1) s += __shfl_xor_sync(0xffffffffu, s, o);
    if (lane == 0) outp[pb * 2 + c] = s + lb[c];
}

// ---------------- launch ----------------------------------------------------
extern "C" void kernel_launch(void* const* d_in, const int* in_sizes, int n_in,
                              void* d_out, int out_size)
{
    const int*   tok      = (const int*)  d_in[0];
    const int*   lens     = (const int*)  d_in[1];
    const float* emb      = (const float*)d_in[2];
    const float* w_ih_l0f = (const float*)d_in[3];
    const float* w_hh_l0f = (const float*)d_in[4];
    const float* b_ih_l0f = (const float*)d_in[5];
    const float* b_hh_l0f = (const float*)d_in[6];
    const float* w_ih_l0b = (const float*)d_in[7];
    const float* w_hh_l0b = (const float*)d_in[8];
    const float* b_ih_l0b = (const float*)d_in[9];
    const float* b_hh_l0b = (const float*)d_in[10];
    const float* w_ih_l1f = (const float*)d_in[11];
    const float* w_hh_l1f = (const float*)d_in[12];
    const float* b_ih_l1f = (const float*)d_in[13];
    const float* b_hh_l1f = (const float*)d_in[14];
    const float* w_ih_l1b = (const float*)d_in[15];
    const float* w_hh_l1b = (const float*)d_in[16];
    const float* b_ih_l1b = (const float*)d_in[17];
    const float* b_hh_l1b = (const float*)d_in[18];
    const float* lin_w    = (const float*)d_in[19];
    const float* lin_b    = (const float*)d_in[20];

    __half *x, *wA, *wB, *whF, *whB, *out0, *hF, *hB;
    float *xpF, *xpB;
    cudaGetSymbolAddress((void**)&x,    g_x);
    cudaGetSymbolAddress((void**)&wA,   g_wA);
    cudaGetSymbolAddress((void**)&wB,   g_wB);
    cudaGetSymbolAddress((void**)&whF,  g_whF);
    cudaGetSymbolAddress((void**)&whB,  g_whB);
    cudaGetSymbolAddress((void**)&xpF,  g_xpF);
    cudaGetSymbolAddress((void**)&xpB,  g_xpB);
    cudaGetSymbolAddress((void**)&out0, g_out0);
    cudaGetSymbolAddress((void**)&hF,   g_hF);
    cudaGetSymbolAddress((void**)&hB,   g_hB);

    cudaFuncSetAttribute(gemm_f16, cudaFuncAttributeMaxDynamicSharedMemorySize, GEMM_SMEM);
    cudaFuncSetAttribute(lstm_layer_kernel, cudaFuncAttributeMaxDynamicSharedMemorySize, LSTM_SMEM);

    dim3 gg(G4_ / 128, M_ / 128);

    // 0. compacted row index + sorted perm + nbt
    build_idx_kernel<<<1, 256>>>(lens);

    // 1. embedding gather -> fp16, K padded to 320
    gather_kernel<<<(M_ * EP_ + 255) / 256, 256>>>(tok, emb, x);

    // 2. convert layer-0 weights, then input projections (Ka = 320)
    conv_f16_pad<<<(G4_ * EP_ + 255) / 256, 256>>>(w_ih_l0f, wA, G4_, E_, EP_);
    conv_f16_pad<<<(G4_ * EP_ + 255) / 256, 256>>>(w_ih_l0b, wB, G4_, E_, EP_);
    conv_f16_v4<<<(G4_ * H_ / 4 + 255) / 256, 256>>>((const float4*)w_hh_l0f, (__half2*)whF, G4_ * H_ / 4);
    conv_f16_v4<<<(G4_ * H_ / 4 + 255) / 256, 256>>>((const float4*)w_hh_l0b, (__half2*)whB, G4_ * H_ / 4);
    gemm_f16<<<gg, 256, GEMM_SMEM>>>(x, wA, b_ih_l0f, b_hh_l0f, xpF, EP_);
    gemm_f16<<<gg, 256, GEMM_SMEM>>>(x, wB, b_ih_l0b, b_hh_l0b, xpB, EP_);

    // 3. layer-0 recurrence (writes [out_f || out_b] as fp16)
    lstm_layer_kernel<<<NCTA_REC, 256, LSTM_SMEM>>>(xpF, xpB, whF, whB, lens,
                                                    out0, hF, hB);

    // 4. convert layer-1 weights, then input projections (Ka = 2048)
    conv_f16_v4<<<(G4_ * 2048 / 4 + 255) / 256, 256>>>((const float4*)w_ih_l1f, (__half2*)wA, G4_ * 2048 / 4);
    conv_f16_v4<<<(G4_ * 2048 / 4 + 255) / 256, 256>>>((const float4*)w_ih_l1b, (__half2*)wB, G4_ * 2048 / 4);
    conv_f16_v4<<<(G4_ * H_ / 4 + 255) / 256, 256>>>((const float4*)w_hh_l1f, (__half2*)whF, G4_ * H_ / 4);
    conv_f16_v4<<<(G4_ * H_ / 4 + 255) / 256, 256>>>((const float4*)w_hh_l1b, (__half2*)whB, G4_ * H_ / 4);
    gemm_f16<<<gg, 256, GEMM_SMEM>>>(out0, wA, b_ih_l1f, b_hh_l1f, xpF, 2 * H_);
    gemm_f16<<<gg, 256, GEMM_SMEM>>>(out0, wB, b_ih_l1b, b_hh_l1b, xpB, 2 * H_);

    // 5. layer-1 recurrence (only final hiddens needed)
    lstm_layer_kernel<<<NCTA_REC, 256, LSTM_SMEM>>>(xpF, xpB, whF, whB, lens,
                                                    (__half*)nullptr, hF, hB);

    // 6. head
    final_linear_kernel<<<8, 256>>>(hF, hB, lin_w, lin_b, (float*)d_out);
}